// round 9
// baseline (speedup 1.0000x reference)
#include <cuda_runtime.h>
#include <math.h>
#include <stdint.h>

// Problem constants
#define DM   512
#define SEQ  2048
#define BB   2
#define NH   8
#define HD   64
#define MTOK (BB*SEQ)     // 4096 tokens
#define NG   (NH*BB)      // 16 attention groups

#define NORMF 0.04419417382415922f  // 1/sqrt(512)

// Scratch (static device globals; allocation is forbidden)
__device__ float g_Qp[MTOK * DM];
__device__ float g_Kp[MTOK * DM];
__device__ float g_Vp[MTOK * DM];
__device__ float g_AO[MTOK * DM];
__device__ float g_KsumP[NG * 8 * HD];

// ---------------------------------------------------------------------------
// tf32 mma.sync.m16n8k8 + split helpers
// ---------------------------------------------------------------------------
__device__ __forceinline__ void mma_tf32(float* c, const uint32_t* a, const uint32_t* b)
{
    asm volatile(
        "mma.sync.aligned.m16n8k8.row.col.f32.tf32.tf32.f32 "
        "{%0,%1,%2,%3}, {%4,%5,%6,%7}, {%8,%9}, {%0,%1,%2,%3};\n"
        : "+f"(c[0]), "+f"(c[1]), "+f"(c[2]), "+f"(c[3])
        : "r"(a[0]), "r"(a[1]), "r"(a[2]), "r"(a[3]), "r"(b[0]), "r"(b[1]));
}

__device__ __forceinline__ uint32_t to_tf32(float x)
{
    uint32_t r;
    asm("cvt.rna.tf32.f32 %0, %1;\n" : "=r"(r) : "f"(x));
    return r;
}

__device__ __forceinline__ void split_tf32(float x, float& hi, float& lo)
{
    hi = __uint_as_float(to_tf32(x));
    lo = x - hi;
}

__device__ __forceinline__ void mma3(float* c,
                                     const uint32_t* ah, const uint32_t* al,
                                     const uint32_t* bh, const uint32_t* bl)
{
    mma_tf32(c, ah, bl);
    mma_tf32(c, al, bh);
    mma_tf32(c, ah, bh);
}

// ---------------------------------------------------------------------------
// Tensor-core NT projection GEMM body (3xTF32), register-pipelined:
// C[4096,512] = A[4096,512] @ W[512,512]^T + bias
// 128x128 CTA tile, BK=32, 8 warps (2m x 4n), warp tile 64x32.
// ---------------------------------------------------------------------------
#define PJ_S 36
#define PJ_SMEM_BYTES (2 * 128 * PJ_S * (int)sizeof(float2))   // 73728

__device__ __forceinline__ void gemm_nt_body(
    const float* __restrict__ A, const float* __restrict__ W,
    const float* __restrict__ bias, float* __restrict__ C,
    float2* sA, float2* sW)
{
    const int tid  = threadIdx.x;
    const int warp = tid >> 5;
    const int lane = tid & 31;
    const int g4   = lane >> 2;
    const int t4   = lane & 3;
    const int wm   = warp >> 2;   // 0..1
    const int wn   = warp & 3;    // 0..3
    const int m0   = blockIdx.y * 128;
    const int n0   = blockIdx.x * 128;

    float acc[4][4][4];
    #pragma unroll
    for (int mf = 0; mf < 4; mf++)
        #pragma unroll
        for (int nf = 0; nf < 4; nf++)
            #pragma unroll
            for (int c = 0; c < 4; c++) acc[mf][nf][c] = 0.f;

    // per-thread load coords (4 float4 of A, 4 of W per k-slab)
    int lr[4], lk[4];
    #pragma unroll
    for (int i = 0; i < 4; i++) {
        int pos = tid + i * 256;          // 0..1023
        lr[i] = pos >> 3;
        lk[i] = (pos & 7) << 2;
    }

    // prologue: prefetch slab 0
    float4 ab[4], wb[4];
    #pragma unroll
    for (int i = 0; i < 4; i++) {
        ab[i] = *(const float4*)&A[(size_t)(m0 + lr[i]) * DM + lk[i]];
        wb[i] = *(const float4*)&W[(size_t)(n0 + lr[i]) * DM + lk[i]];
    }

    for (int kt = 0; kt < DM / 32; kt++) {
        __syncthreads();
        #pragma unroll
        for (int i = 0; i < 4; i++) {
            float4 s0, s1;
            split_tf32(ab[i].x, s0.x, s0.y); split_tf32(ab[i].y, s0.z, s0.w);
            split_tf32(ab[i].z, s1.x, s1.y); split_tf32(ab[i].w, s1.z, s1.w);
            *(float4*)&sA[lr[i] * PJ_S + lk[i]]     = s0;
            *(float4*)&sA[lr[i] * PJ_S + lk[i] + 2] = s1;
            split_tf32(wb[i].x, s0.x, s0.y); split_tf32(wb[i].y, s0.z, s0.w);
            split_tf32(wb[i].z, s1.x, s1.y); split_tf32(wb[i].w, s1.z, s1.w);
            *(float4*)&sW[lr[i] * PJ_S + lk[i]]     = s0;
            *(float4*)&sW[lr[i] * PJ_S + lk[i] + 2] = s1;
        }
        __syncthreads();

        // prefetch next slab while mma runs
        if (kt + 1 < DM / 32) {
            const int k0n = (kt + 1) * 32;
            #pragma unroll
            for (int i = 0; i < 4; i++) {
                ab[i] = *(const float4*)&A[(size_t)(m0 + lr[i]) * DM + k0n + lk[i]];
                wb[i] = *(const float4*)&W[(size_t)(n0 + lr[i]) * DM + k0n + lk[i]];
            }
        }

        #pragma unroll
        for (int kk = 0; kk < 4; kk++) {
            const int kc = kk * 8 + t4;
            uint32_t ah[4][4], al[4][4];
            #pragma unroll
            for (int mf = 0; mf < 4; mf++) {
                const int rb = wm * 64 + mf * 16;
                float2 e0 = sA[(rb + g4)     * PJ_S + kc];
                float2 e1 = sA[(rb + g4 + 8) * PJ_S + kc];
                float2 e2 = sA[(rb + g4)     * PJ_S + kc + 4];
                float2 e3 = sA[(rb + g4 + 8) * PJ_S + kc + 4];
                ah[mf][0] = __float_as_uint(e0.x); al[mf][0] = __float_as_uint(e0.y);
                ah[mf][1] = __float_as_uint(e1.x); al[mf][1] = __float_as_uint(e1.y);
                ah[mf][2] = __float_as_uint(e2.x); al[mf][2] = __float_as_uint(e2.y);
                ah[mf][3] = __float_as_uint(e3.x); al[mf][3] = __float_as_uint(e3.y);
            }
            #pragma unroll
            for (int nf = 0; nf < 4; nf++) {
                const int nr = wn * 32 + nf * 8 + g4;
                float2 b0 = sW[nr * PJ_S + kc];
                float2 b1 = sW[nr * PJ_S + kc + 4];
                uint32_t bh[2] = {__float_as_uint(b0.x), __float_as_uint(b1.x)};
                uint32_t bl[2] = {__float_as_uint(b0.y), __float_as_uint(b1.y)};
                #pragma unroll
                for (int mf = 0; mf < 4; mf++)
                    mma3(acc[mf][nf], ah[mf], al[mf], bh, bl);
            }
        }
    }

    #pragma unroll
    for (int nf = 0; nf < 4; nf++) {
        const int col = n0 + wn * 32 + nf * 8 + 2 * t4;
        const float b0 = bias[col], b1 = bias[col + 1];
        #pragma unroll
        for (int mf = 0; mf < 4; mf++) {
            const int r0 = m0 + wm * 64 + mf * 16 + g4;
            *(float2*)&C[(size_t)r0 * DM + col] =
                make_float2(acc[mf][nf][0] + b0, acc[mf][nf][1] + b1);
            *(float2*)&C[(size_t)(r0 + 8) * DM + col] =
                make_float2(acc[mf][nf][2] + b0, acc[mf][nf][3] + b1);
        }
    }
}

// Fused Q/K/V projection: blockIdx.z selects which projection.
__global__ __launch_bounds__(256) void gemm_qkv(
    const float* __restrict__ x, const float* __restrict__ y,
    const float* __restrict__ q_w, const float* __restrict__ q_b,
    const float* __restrict__ k_w, const float* __restrict__ k_b,
    const float* __restrict__ v_w, const float* __restrict__ v_b,
    float* __restrict__ Qp, float* __restrict__ Kp, float* __restrict__ Vp)
{
    extern __shared__ float2 pj_sm[];
    const float *A, *W, *bias;
    float* C;
    if (blockIdx.z == 0)      { A = x; W = q_w; bias = q_b; C = Qp; }
    else if (blockIdx.z == 1) { A = y; W = k_w; bias = k_b; C = Kp; }
    else                      { A = y; W = v_w; bias = v_b; C = Vp; }
    gemm_nt_body(A, W, bias, C, pj_sm, pj_sm + 128 * PJ_S);
}

// Output projection
__global__ __launch_bounds__(256) void gemm_oproj(
    const float* __restrict__ A, const float* __restrict__ W,
    const float* __restrict__ bias, float* __restrict__ C)
{
    extern __shared__ float2 pj_sm[];
    gemm_nt_body(A, W, bias, C, pj_sm, pj_sm + 128 * PJ_S);
}

// ---------------------------------------------------------------------------
// K column-sum partials
// ---------------------------------------------------------------------------
__global__ __launch_bounds__(256) void ksum_kernel(const float* __restrict__ Kp,
                                                   float* __restrict__ out)
{
    const int g  = blockIdx.x;
    const int ch = blockIdx.y;
    const int d  = threadIdx.x & 63;
    const int rc = threadIdx.x >> 6;
    const float* Kg = Kp + ((size_t)g * SEQ + ch * 256) * HD;
    float s = 0.f;
    #pragma unroll 8
    for (int r = rc; r < 256; r += 4) s += Kg[r * HD + d];
    __shared__ float red[256];
    red[threadIdx.x] = s;
    __syncthreads();
    if (rc == 0)
        out[(g * 8 + ch) * HD + d] = red[d] + red[64 + d] + red[128 + d] + red[192 + d];
}

// ---------------------------------------------------------------------------
// Single-pass fused attention, 3xTF32, (hi,lo)-interleaved K/V SMEM,
// register double-buffered global loads. P split-at-write into SMEM.
// ---------------------------------------------------------------------------
#define AT_S 68
#define SM_F2  (64*AT_S + 64*AT_S + 4*16*AT_S)
#define SM_BYTES (SM_F2 * 8)                    // 104448 B

__global__ __launch_bounds__(128, 2) void attn_fused(
    const float* __restrict__ Qp, const float* __restrict__ Kp,
    const float* __restrict__ Vp, const float* __restrict__ KsP,
    float* __restrict__ AO)
{
    extern __shared__ float2 sm2[];
    float2* sK2 = sm2;                    // [64][AT_S]
    float2* sV2 = sK2 + 64 * AT_S;        // [64][AT_S]
    float2* sP_all = sV2 + 64 * AT_S;     // 4 x [16][AT_S]

    const int tid  = threadIdx.x;
    const int warp = tid >> 5;
    const int lane = tid & 31;
    const int g4   = lane >> 2;
    const int t4   = lane & 3;

    const int mt  = blockIdx.x;
    const int grp = blockIdx.y;
    const float* Qg = Qp + (size_t)grp * SEQ * HD;
    const float* Kg = Kp + (size_t)grp * SEQ * HD;
    const float* Vg = Vp + (size_t)grp * SEQ * HD;
    float*       Og = AO + (size_t)grp * SEQ * HD;

    const int m0 = mt * 64;
    const int wrow = warp * 16;
    float2* sP2 = sP_all + warp * 16 * AT_S;

    // --- Q fragments (registers) + row means via K column-sums ---
    const int row0 = m0 + wrow + g4;
    const int row1 = row0 + 8;
    uint32_t qah[8][4], qal[8][4];
    float mdot0 = 0.f, mdot1 = 0.f;

    #pragma unroll
    for (int kk = 0; kk < 8; kk++) {
        #pragma unroll
        for (int e = 0; e < 2; e++) {
            const int col = kk * 8 + t4 + e * 4;
            float ks = 0.f;
            #pragma unroll
            for (int c = 0; c < 8; c++)
                ks += KsP[(grp * 8 + c) * HD + col];
            float q0 = Qg[(size_t)row0 * HD + col];
            float q1 = Qg[(size_t)row1 * HD + col];
            mdot0 += q0 * ks;
            mdot1 += q1 * ks;
            float h, l;
            split_tf32(q0 * NORMF, h, l);
            qah[kk][e * 2] = __float_as_uint(h);
            qal[kk][e * 2] = __float_as_uint(l);
            split_tf32(q1 * NORMF, h, l);
            qah[kk][e * 2 + 1] = __float_as_uint(h);
            qal[kk][e * 2 + 1] = __float_as_uint(l);
        }
    }
    #pragma unroll
    for (int o = 1; o <= 2; o <<= 1) {
        mdot0 += __shfl_xor_sync(0xffffffffu, mdot0, o);
        mdot1 += __shfl_xor_sync(0xffffffffu, mdot1, o);
    }
    const float mean0 = mdot0 * (NORMF / (float)SEQ);
    const float mean1 = mdot1 * (NORMF / (float)SEQ);

    // --- streaming loop with register double-buffered K/V loads ---
    float oacc[8][4];
    #pragma unroll
    for (int j = 0; j < 8; j++)
        #pragma unroll
        for (int c = 0; c < 4; c++) oacc[j][c] = 0.f;
    float den0 = 0.f, den1 = 0.f;

    // per-thread load coords (8 float4 of K, 8 of V per tile)
    // j = tid + i*128 -> r = j>>4, c4 = (j&15)<<2
    float4 kbuf[8], vbuf[8];
    #pragma unroll
    for (int i = 0; i < 8; i++) {
        int j = tid + i * 128;
        int r = j >> 4, c4 = (j & 15) << 2;
        kbuf[i] = *(const float4*)&Kg[(size_t)r * HD + c4];
        vbuf[i] = *(const float4*)&Vg[(size_t)r * HD + c4];
    }

    for (int kt = 0; kt < SEQ / 64; kt++) {
        __syncthreads();
        // split buffered tile into SMEM
        #pragma unroll
        for (int i = 0; i < 8; i++) {
            int j = tid + i * 128;
            int r = j >> 4, c4 = (j & 15) << 2;
            float4 s0, s1;
            split_tf32(kbuf[i].x, s0.x, s0.y); split_tf32(kbuf[i].y, s0.z, s0.w);
            split_tf32(kbuf[i].z, s1.x, s1.y); split_tf32(kbuf[i].w, s1.z, s1.w);
            *(float4*)&sK2[r * AT_S + c4]     = s0;
            *(float4*)&sK2[r * AT_S + c4 + 2] = s1;
            split_tf32(vbuf[i].x, s0.x, s0.y); split_tf32(vbuf[i].y, s0.z, s0.w);
            split_tf32(vbuf[i].z, s1.x, s1.y); split_tf32(vbuf[i].w, s1.z, s1.w);
            *(float4*)&sV2[r * AT_S + c4]     = s0;
            *(float4*)&sV2[r * AT_S + c4 + 2] = s1;
        }
        __syncthreads();

        // prefetch next tile while mma runs
        if (kt + 1 < SEQ / 64) {
            const size_t base = (size_t)(kt + 1) * 64;
            #pragma unroll
            for (int i = 0; i < 8; i++) {
                int j = tid + i * 128;
                int r = j >> 4, c4 = (j & 15) << 2;
                kbuf[i] = *(const float4*)&Kg[(base + r) * HD + c4];
                vbuf[i] = *(const float4*)&Vg[(base + r) * HD + c4];
            }
        }

        // S = Qs @ K^T (3xTF32)
        float sacc[8][4];
        #pragma unroll
        for (int j = 0; j < 8; j++)
            #pragma unroll
            for (int c = 0; c < 4; c++) sacc[j][c] = 0.f;

        #pragma unroll
        for (int kk = 0; kk < 8; kk++) {
            const int k0 = kk * 8;
            #pragma unroll
            for (int j = 0; j < 8; j++) {
                const int brow = j * 8 + g4;
                float2 b0 = sK2[brow * AT_S + k0 + t4];
                float2 b1 = sK2[brow * AT_S + k0 + t4 + 4];
                uint32_t bh[2] = {__float_as_uint(b0.x), __float_as_uint(b1.x)};
                uint32_t bl[2] = {__float_as_uint(b0.y), __float_as_uint(b1.y)};
                mma3(sacc[j], qah[kk], qal[kk], bh, bl);
            }
        }

        // mask + exp -> split P into smem; accumulate denom
        #pragma unroll
        for (int j = 0; j < 8; j++) {
            float p0 = (sacc[j][0] > mean0) ? __expf(sacc[j][0]) : 0.f;
            float p1 = (sacc[j][1] > mean0) ? __expf(sacc[j][1]) : 0.f;
            float p2 = (sacc[j][2] > mean1) ? __expf(sacc[j][2]) : 0.f;
            float p3 = (sacc[j][3] > mean1) ? __expf(sacc[j][3]) : 0.f;
            den0 += p0 + p1;
            den1 += p2 + p3;
            float4 s;
            split_tf32(p0, s.x, s.y); split_tf32(p1, s.z, s.w);
            *(float4*)&sP2[g4 * AT_S + j * 8 + 2 * t4] = s;
            split_tf32(p2, s.x, s.y); split_tf32(p3, s.z, s.w);
            *(float4*)&sP2[(g4 + 8) * AT_S + j * 8 + 2 * t4] = s;
        }
        __syncwarp();

        // O += P @ V (3xTF32)
        #pragma unroll
        for (int kk = 0; kk < 8; kk++) {
            const int k0 = kk * 8;
            float2 a0 = sP2[g4       * AT_S + k0 + t4];
            float2 a1 = sP2[(g4 + 8) * AT_S + k0 + t4];
            float2 a2 = sP2[g4       * AT_S + k0 + t4 + 4];
            float2 a3 = sP2[(g4 + 8) * AT_S + k0 + t4 + 4];
            uint32_t ah[4] = {__float_as_uint(a0.x), __float_as_uint(a1.x),
                              __float_as_uint(a2.x), __float_as_uint(a3.x)};
            uint32_t al[4] = {__float_as_uint(a0.y), __float_as_uint(a1.y),
                              __float_as_uint(a2.y), __float_as_uint(a3.y)};
            #pragma unroll
            for (int j = 0; j < 8; j++) {
                const int bcol = j * 8 + g4;
                float2 b0 = sV2[(k0 + t4)     * AT_S + bcol];
                float2 b1 = sV2[(k0 + t4 + 4) * AT_S + bcol];
                uint32_t bh[2] = {__float_as_uint(b0.x), __float_as_uint(b1.x)};
                uint32_t bl[2] = {__float_as_uint(b0.y), __float_as_uint(b1.y)};
                mma3(oacc[j], ah, al, bh, bl);
            }
        }
    }

    // reduce denominators, normalize, write out
    #pragma unroll
    for (int o = 1; o <= 2; o <<= 1) {
        den0 += __shfl_xor_sync(0xffffffffu, den0, o);
        den1 += __shfl_xor_sync(0xffffffffu, den1, o);
    }
    const float inv0 = 1.f / den0;
    const float inv1 = 1.f / den1;

    #pragma unroll
    for (int j = 0; j < 8; j++) {
        const int col = j * 8 + 2 * t4;
        *(float2*)&Og[(size_t)row0 * HD + col] =
            make_float2(oacc[j][0] * inv0, oacc[j][1] * inv0);
        *(float2*)&Og[(size_t)row1 * HD + col] =
            make_float2(oacc[j][2] * inv1, oacc[j][3] * inv1);
    }
}

// ---------------------------------------------------------------------------
// Launch
// ---------------------------------------------------------------------------
extern "C" void kernel_launch(void* const* d_in, const int* in_sizes, int n_in,
                              void* d_out, int out_size)
{
    const float* x   = (const float*)d_in[0];
    const float* y   = (const float*)d_in[1];
    const float* q_w = (const float*)d_in[2];
    const float* q_b = (const float*)d_in[3];
    const float* k_w = (const float*)d_in[4];
    const float* k_b = (const float*)d_in[5];
    const float* v_w = (const float*)d_in[6];
    const float* v_b = (const float*)d_in[7];
    const float* o_w = (const float*)d_in[8];
    const float* o_b = (const float*)d_in[9];
    float* out = (float*)d_out;

    float *Qp, *Kp, *Vp, *AO, *KsP;
    cudaGetSymbolAddress((void**)&Qp, g_Qp);
    cudaGetSymbolAddress((void**)&Kp, g_Kp);
    cudaGetSymbolAddress((void**)&Vp, g_Vp);
    cudaGetSymbolAddress((void**)&AO, g_AO);
    cudaGetSymbolAddress((void**)&KsP, g_KsumP);

    static int smem_set = 0;
    if (!smem_set) {
        cudaFuncSetAttribute(attn_fused,
                             cudaFuncAttributeMaxDynamicSharedMemorySize, SM_BYTES);
        cudaFuncSetAttribute(gemm_qkv,
                             cudaFuncAttributeMaxDynamicSharedMemorySize, PJ_SMEM_BYTES);
        cudaFuncSetAttribute(gemm_oproj,
                             cudaFuncAttributeMaxDynamicSharedMemorySize, PJ_SMEM_BYTES);
        smem_set = 1;
    }

    // Fused Q/K/V projections (tensor core, 3xTF32) — one launch, 384 CTAs
    gemm_qkv<<<dim3(4, 32, 3), 256, PJ_SMEM_BYTES>>>(
        x, y, q_w, q_b, k_w, k_b, v_w, v_b, Qp, Kp, Vp);

    // K column-sum partials (for mean thresholds)
    ksum_kernel<<<dim3(NG, 8), 256>>>(Kp, KsP);

    // Fused single-pass attention
    attn_fused<<<dim3(SEQ / 64, NG), 128, SM_BYTES>>>(Qp, Kp, Vp, KsP, AO);

    // Output projection (tensor core, 3xTF32)
    gemm_oproj<<<dim3(4, 32), 256, PJ_SMEM_BYTES>>>(AO, o_w, o_b, out);
}

// round 10
// speedup vs baseline: 1.1421x; 1.1421x over previous
#include <cuda_runtime.h>
#include <math.h>
#include <stdint.h>

// Problem constants
#define DM   512
#define SEQ  2048
#define BB   2
#define NH   8
#define HD   64
#define MTOK (BB*SEQ)     // 4096 tokens
#define NG   (NH*BB)      // 16 attention groups

#define NORMF 0.04419417382415922f  // 1/sqrt(512)

// Scratch (static device globals; allocation is forbidden)
__device__ float g_Qp[MTOK * DM];
__device__ float g_Kp[MTOK * DM];
__device__ float g_Vp[MTOK * DM];
__device__ float g_AO[MTOK * DM];
__device__ float g_KsumP[NG * 8 * HD];

// ---------------------------------------------------------------------------
// tf32 mma.sync.m16n8k8 + split helpers
// ---------------------------------------------------------------------------
__device__ __forceinline__ void mma_tf32(float* c, const uint32_t* a, const uint32_t* b)
{
    asm volatile(
        "mma.sync.aligned.m16n8k8.row.col.f32.tf32.tf32.f32 "
        "{%0,%1,%2,%3}, {%4,%5,%6,%7}, {%8,%9}, {%0,%1,%2,%3};\n"
        : "+f"(c[0]), "+f"(c[1]), "+f"(c[2]), "+f"(c[3])
        : "r"(a[0]), "r"(a[1]), "r"(a[2]), "r"(a[3]), "r"(b[0]), "r"(b[1]));
}

__device__ __forceinline__ uint32_t to_tf32(float x)
{
    uint32_t r;
    asm("cvt.rna.tf32.f32 %0, %1;\n" : "=r"(r) : "f"(x));
    return r;
}

__device__ __forceinline__ void split_tf32(float x, float& hi, float& lo)
{
    hi = __uint_as_float(to_tf32(x));
    lo = x - hi;
}

__device__ __forceinline__ void mma3(float* c,
                                     const uint32_t* ah, const uint32_t* al,
                                     const uint32_t* bh, const uint32_t* bl)
{
    mma_tf32(c, ah, bl);
    mma_tf32(c, al, bh);
    mma_tf32(c, ah, bh);
}

// ---------------------------------------------------------------------------
// Tensor-core NT projection GEMM body (3xTF32), register-pipelined.
// ---------------------------------------------------------------------------
#define PJ_S 36
#define PJ_SMEM_BYTES (2 * 128 * PJ_S * (int)sizeof(float2))   // 73728

__device__ __forceinline__ void gemm_nt_body(
    const float* __restrict__ A, const float* __restrict__ W,
    const float* __restrict__ bias, float* __restrict__ C,
    float2* sA, float2* sW)
{
    const int tid  = threadIdx.x;
    const int warp = tid >> 5;
    const int lane = tid & 31;
    const int g4   = lane >> 2;
    const int t4   = lane & 3;
    const int wm   = warp >> 2;   // 0..1
    const int wn   = warp & 3;    // 0..3
    const int m0   = blockIdx.y * 128;
    const int n0   = blockIdx.x * 128;

    float acc[4][4][4];
    #pragma unroll
    for (int mf = 0; mf < 4; mf++)
        #pragma unroll
        for (int nf = 0; nf < 4; nf++)
            #pragma unroll
            for (int c = 0; c < 4; c++) acc[mf][nf][c] = 0.f;

    int lr[4], lk[4];
    #pragma unroll
    for (int i = 0; i < 4; i++) {
        int pos = tid + i * 256;
        lr[i] = pos >> 3;
        lk[i] = (pos & 7) << 2;
    }

    float4 ab[4], wb[4];
    #pragma unroll
    for (int i = 0; i < 4; i++) {
        ab[i] = *(const float4*)&A[(size_t)(m0 + lr[i]) * DM + lk[i]];
        wb[i] = *(const float4*)&W[(size_t)(n0 + lr[i]) * DM + lk[i]];
    }

    for (int kt = 0; kt < DM / 32; kt++) {
        __syncthreads();
        #pragma unroll
        for (int i = 0; i < 4; i++) {
            float4 s0, s1;
            split_tf32(ab[i].x, s0.x, s0.y); split_tf32(ab[i].y, s0.z, s0.w);
            split_tf32(ab[i].z, s1.x, s1.y); split_tf32(ab[i].w, s1.z, s1.w);
            *(float4*)&sA[lr[i] * PJ_S + lk[i]]     = s0;
            *(float4*)&sA[lr[i] * PJ_S + lk[i] + 2] = s1;
            split_tf32(wb[i].x, s0.x, s0.y); split_tf32(wb[i].y, s0.z, s0.w);
            split_tf32(wb[i].z, s1.x, s1.y); split_tf32(wb[i].w, s1.z, s1.w);
            *(float4*)&sW[lr[i] * PJ_S + lk[i]]     = s0;
            *(float4*)&sW[lr[i] * PJ_S + lk[i] + 2] = s1;
        }
        __syncthreads();

        if (kt + 1 < DM / 32) {
            const int k0n = (kt + 1) * 32;
            #pragma unroll
            for (int i = 0; i < 4; i++) {
                ab[i] = *(const float4*)&A[(size_t)(m0 + lr[i]) * DM + k0n + lk[i]];
                wb[i] = *(const float4*)&W[(size_t)(n0 + lr[i]) * DM + k0n + lk[i]];
            }
        }

        #pragma unroll
        for (int kk = 0; kk < 4; kk++) {
            const int kc = kk * 8 + t4;
            uint32_t ah[4][4], al[4][4];
            #pragma unroll
            for (int mf = 0; mf < 4; mf++) {
                const int rb = wm * 64 + mf * 16;
                float2 e0 = sA[(rb + g4)     * PJ_S + kc];
                float2 e1 = sA[(rb + g4 + 8) * PJ_S + kc];
                float2 e2 = sA[(rb + g4)     * PJ_S + kc + 4];
                float2 e3 = sA[(rb + g4 + 8) * PJ_S + kc + 4];
                ah[mf][0] = __float_as_uint(e0.x); al[mf][0] = __float_as_uint(e0.y);
                ah[mf][1] = __float_as_uint(e1.x); al[mf][1] = __float_as_uint(e1.y);
                ah[mf][2] = __float_as_uint(e2.x); al[mf][2] = __float_as_uint(e2.y);
                ah[mf][3] = __float_as_uint(e3.x); al[mf][3] = __float_as_uint(e3.y);
            }
            #pragma unroll
            for (int nf = 0; nf < 4; nf++) {
                const int nr = wn * 32 + nf * 8 + g4;
                float2 b0 = sW[nr * PJ_S + kc];
                float2 b1 = sW[nr * PJ_S + kc + 4];
                uint32_t bh[2] = {__float_as_uint(b0.x), __float_as_uint(b1.x)};
                uint32_t bl[2] = {__float_as_uint(b0.y), __float_as_uint(b1.y)};
                #pragma unroll
                for (int mf = 0; mf < 4; mf++)
                    mma3(acc[mf][nf], ah[mf], al[mf], bh, bl);
            }
        }
    }

    #pragma unroll
    for (int nf = 0; nf < 4; nf++) {
        const int col = n0 + wn * 32 + nf * 8 + 2 * t4;
        const float b0 = bias[col], b1 = bias[col + 1];
        #pragma unroll
        for (int mf = 0; mf < 4; mf++) {
            const int r0 = m0 + wm * 64 + mf * 16 + g4;
            *(float2*)&C[(size_t)r0 * DM + col] =
                make_float2(acc[mf][nf][0] + b0, acc[mf][nf][1] + b1);
            *(float2*)&C[(size_t)(r0 + 8) * DM + col] =
                make_float2(acc[mf][nf][2] + b0, acc[mf][nf][3] + b1);
        }
    }
}

// Fused Q/K/V projection: blockIdx.z selects which projection.
__global__ __launch_bounds__(256) void gemm_qkv(
    const float* __restrict__ x, const float* __restrict__ y,
    const float* __restrict__ q_w, const float* __restrict__ q_b,
    const float* __restrict__ k_w, const float* __restrict__ k_b,
    const float* __restrict__ v_w, const float* __restrict__ v_b,
    float* __restrict__ Qp, float* __restrict__ Kp, float* __restrict__ Vp)
{
    extern __shared__ float2 pj_sm[];
    const float *A, *W, *bias;
    float* C;
    if (blockIdx.z == 0)      { A = x; W = q_w; bias = q_b; C = Qp; }
    else if (blockIdx.z == 1) { A = y; W = k_w; bias = k_b; C = Kp; }
    else                      { A = y; W = v_w; bias = v_b; C = Vp; }
    gemm_nt_body(A, W, bias, C, pj_sm, pj_sm + 128 * PJ_S);
}

__global__ __launch_bounds__(256) void gemm_oproj(
    const float* __restrict__ A, const float* __restrict__ W,
    const float* __restrict__ bias, float* __restrict__ C)
{
    extern __shared__ float2 pj_sm[];
    gemm_nt_body(A, W, bias, C, pj_sm, pj_sm + 128 * PJ_S);
}

// ---------------------------------------------------------------------------
// K column-sum partials
// ---------------------------------------------------------------------------
__global__ __launch_bounds__(256) void ksum_kernel(const float* __restrict__ Kp,
                                                   float* __restrict__ out)
{
    const int g  = blockIdx.x;
    const int ch = blockIdx.y;
    const int d  = threadIdx.x & 63;
    const int rc = threadIdx.x >> 6;
    const float* Kg = Kp + ((size_t)g * SEQ + ch * 256) * HD;
    float s = 0.f;
    #pragma unroll 8
    for (int r = rc; r < 256; r += 4) s += Kg[r * HD + d];
    __shared__ float red[256];
    red[threadIdx.x] = s;
    __syncthreads();
    if (rc == 0)
        out[(g * 8 + ch) * HD + d] = red[d] + red[64 + d] + red[128 + d] + red[192 + d];
}

// ---------------------------------------------------------------------------
// Single-pass fused attention, 3xTF32, (hi,lo)-interleaved K/V/P SMEM.
// CTA = 128 query rows (256 threads, 8 warps x 16 rows) — per-tile overhead
// (K/V load, split, syncs) amortized over 2x the mma work vs 64-row CTA.
// ---------------------------------------------------------------------------
#define AT_S 68
#define SM_F2  (64*AT_S + 64*AT_S + 8*16*AT_S)
#define SM_BYTES (SM_F2 * 8)                    // 139264 B

__global__ __launch_bounds__(256, 1) void attn_fused(
    const float* __restrict__ Qp, const float* __restrict__ Kp,
    const float* __restrict__ Vp, const float* __restrict__ KsP,
    float* __restrict__ AO)
{
    extern __shared__ float2 sm2[];
    float2* sK2 = sm2;                    // [64][AT_S]
    float2* sV2 = sK2 + 64 * AT_S;        // [64][AT_S]
    float2* sP_all = sV2 + 64 * AT_S;     // 8 x [16][AT_S]

    const int tid  = threadIdx.x;
    const int warp = tid >> 5;
    const int lane = tid & 31;
    const int g4   = lane >> 2;
    const int t4   = lane & 3;

    const int mt  = blockIdx.x;
    const int grp = blockIdx.y;
    const float* Qg = Qp + (size_t)grp * SEQ * HD;
    const float* Kg = Kp + (size_t)grp * SEQ * HD;
    const float* Vg = Vp + (size_t)grp * SEQ * HD;
    float*       Og = AO + (size_t)grp * SEQ * HD;

    const int m0 = mt * 128;
    const int wrow = warp * 16;           // 0..112
    float2* sP2 = sP_all + warp * 16 * AT_S;

    // --- Q fragments (registers) + row means via K column-sums ---
    const int row0 = m0 + wrow + g4;
    const int row1 = row0 + 8;
    uint32_t qah[8][4], qal[8][4];
    float mdot0 = 0.f, mdot1 = 0.f;

    #pragma unroll
    for (int kk = 0; kk < 8; kk++) {
        #pragma unroll
        for (int e = 0; e < 2; e++) {
            const int col = kk * 8 + t4 + e * 4;
            float ks = 0.f;
            #pragma unroll
            for (int c = 0; c < 8; c++)
                ks += KsP[(grp * 8 + c) * HD + col];
            float q0 = Qg[(size_t)row0 * HD + col];
            float q1 = Qg[(size_t)row1 * HD + col];
            mdot0 += q0 * ks;
            mdot1 += q1 * ks;
            float h, l;
            split_tf32(q0 * NORMF, h, l);
            qah[kk][e * 2] = __float_as_uint(h);
            qal[kk][e * 2] = __float_as_uint(l);
            split_tf32(q1 * NORMF, h, l);
            qah[kk][e * 2 + 1] = __float_as_uint(h);
            qal[kk][e * 2 + 1] = __float_as_uint(l);
        }
    }
    #pragma unroll
    for (int o = 1; o <= 2; o <<= 1) {
        mdot0 += __shfl_xor_sync(0xffffffffu, mdot0, o);
        mdot1 += __shfl_xor_sync(0xffffffffu, mdot1, o);
    }
    const float mean0 = mdot0 * (NORMF / (float)SEQ);
    const float mean1 = mdot1 * (NORMF / (float)SEQ);

    // --- streaming loop ---
    float oacc[8][4];
    #pragma unroll
    for (int j = 0; j < 8; j++)
        #pragma unroll
        for (int c = 0; c < 4; c++) oacc[j][c] = 0.f;
    float den0 = 0.f, den1 = 0.f;

    for (int kt = 0; kt < SEQ / 64; kt++) {
        __syncthreads();
        // cooperative load + single split of K and V tiles (4 float4/thread)
        #pragma unroll
        for (int i = 0; i < 4; i++) {
            int j = tid + i * 256;
            int r = j >> 4, c4 = (j & 15) << 2;
            float4 kv = *(const float4*)&Kg[(size_t)(kt * 64 + r) * HD + c4];
            float4 vv = *(const float4*)&Vg[(size_t)(kt * 64 + r) * HD + c4];
            float4 s0, s1;
            split_tf32(kv.x, s0.x, s0.y); split_tf32(kv.y, s0.z, s0.w);
            split_tf32(kv.z, s1.x, s1.y); split_tf32(kv.w, s1.z, s1.w);
            *(float4*)&sK2[r * AT_S + c4]     = s0;
            *(float4*)&sK2[r * AT_S + c4 + 2] = s1;
            split_tf32(vv.x, s0.x, s0.y); split_tf32(vv.y, s0.z, s0.w);
            split_tf32(vv.z, s1.x, s1.y); split_tf32(vv.w, s1.z, s1.w);
            *(float4*)&sV2[r * AT_S + c4]     = s0;
            *(float4*)&sV2[r * AT_S + c4 + 2] = s1;
        }
        __syncthreads();

        // S = Qs @ K^T (3xTF32)
        float sacc[8][4];
        #pragma unroll
        for (int j = 0; j < 8; j++)
            #pragma unroll
            for (int c = 0; c < 4; c++) sacc[j][c] = 0.f;

        #pragma unroll
        for (int kk = 0; kk < 8; kk++) {
            const int k0 = kk * 8;
            #pragma unroll
            for (int j = 0; j < 8; j++) {
                const int brow = j * 8 + g4;
                float2 b0 = sK2[brow * AT_S + k0 + t4];
                float2 b1 = sK2[brow * AT_S + k0 + t4 + 4];
                uint32_t bh[2] = {__float_as_uint(b0.x), __float_as_uint(b1.x)};
                uint32_t bl[2] = {__float_as_uint(b0.y), __float_as_uint(b1.y)};
                mma3(sacc[j], qah[kk], qal[kk], bh, bl);
            }
        }

        // mask + exp -> split P into smem; accumulate denom
        #pragma unroll
        for (int j = 0; j < 8; j++) {
            float p0 = (sacc[j][0] > mean0) ? __expf(sacc[j][0]) : 0.f;
            float p1 = (sacc[j][1] > mean0) ? __expf(sacc[j][1]) : 0.f;
            float p2 = (sacc[j][2] > mean1) ? __expf(sacc[j][2]) : 0.f;
            float p3 = (sacc[j][3] > mean1) ? __expf(sacc[j][3]) : 0.f;
            den0 += p0 + p1;
            den1 += p2 + p3;
            float4 s;
            split_tf32(p0, s.x, s.y); split_tf32(p1, s.z, s.w);
            *(float4*)&sP2[g4 * AT_S + j * 8 + 2 * t4] = s;
            split_tf32(p2, s.x, s.y); split_tf32(p3, s.z, s.w);
            *(float4*)&sP2[(g4 + 8) * AT_S + j * 8 + 2 * t4] = s;
        }
        __syncwarp();

        // O += P @ V (3xTF32)
        #pragma unroll
        for (int kk = 0; kk < 8; kk++) {
            const int k0 = kk * 8;
            float2 a0 = sP2[g4       * AT_S + k0 + t4];
            float2 a1 = sP2[(g4 + 8) * AT_S + k0 + t4];
            float2 a2 = sP2[g4       * AT_S + k0 + t4 + 4];
            float2 a3 = sP2[(g4 + 8) * AT_S + k0 + t4 + 4];
            uint32_t ah[4] = {__float_as_uint(a0.x), __float_as_uint(a1.x),
                              __float_as_uint(a2.x), __float_as_uint(a3.x)};
            uint32_t al[4] = {__float_as_uint(a0.y), __float_as_uint(a1.y),
                              __float_as_uint(a2.y), __float_as_uint(a3.y)};
            #pragma unroll
            for (int j = 0; j < 8; j++) {
                const int bcol = j * 8 + g4;
                float2 b0 = sV2[(k0 + t4)     * AT_S + bcol];
                float2 b1 = sV2[(k0 + t4 + 4) * AT_S + bcol];
                uint32_t bh[2] = {__float_as_uint(b0.x), __float_as_uint(b1.x)};
                uint32_t bl[2] = {__float_as_uint(b0.y), __float_as_uint(b1.y)};
                mma3(oacc[j], ah, al, bh, bl);
            }
        }
    }

    // reduce denominators, normalize, write out
    #pragma unroll
    for (int o = 1; o <= 2; o <<= 1) {
        den0 += __shfl_xor_sync(0xffffffffu, den0, o);
        den1 += __shfl_xor_sync(0xffffffffu, den1, o);
    }
    const float inv0 = 1.f / den0;
    const float inv1 = 1.f / den1;

    #pragma unroll
    for (int j = 0; j < 8; j++) {
        const int col = j * 8 + 2 * t4;
        *(float2*)&Og[(size_t)row0 * HD + col] =
            make_float2(oacc[j][0] * inv0, oacc[j][1] * inv0);
        *(float2*)&Og[(size_t)row1 * HD + col] =
            make_float2(oacc[j][2] * inv1, oacc[j][3] * inv1);
    }
}

// ---------------------------------------------------------------------------
// Launch
// ---------------------------------------------------------------------------
extern "C" void kernel_launch(void* const* d_in, const int* in_sizes, int n_in,
                              void* d_out, int out_size)
{
    const float* x   = (const float*)d_in[0];
    const float* y   = (const float*)d_in[1];
    const float* q_w = (const float*)d_in[2];
    const float* q_b = (const float*)d_in[3];
    const float* k_w = (const float*)d_in[4];
    const float* k_b = (const float*)d_in[5];
    const float* v_w = (const float*)d_in[6];
    const float* v_b = (const float*)d_in[7];
    const float* o_w = (const float*)d_in[8];
    const float* o_b = (const float*)d_in[9];
    float* out = (float*)d_out;

    float *Qp, *Kp, *Vp, *AO, *KsP;
    cudaGetSymbolAddress((void**)&Qp, g_Qp);
    cudaGetSymbolAddress((void**)&Kp, g_Kp);
    cudaGetSymbolAddress((void**)&Vp, g_Vp);
    cudaGetSymbolAddress((void**)&AO, g_AO);
    cudaGetSymbolAddress((void**)&KsP, g_KsumP);

    static int smem_set = 0;
    if (!smem_set) {
        cudaFuncSetAttribute(attn_fused,
                             cudaFuncAttributeMaxDynamicSharedMemorySize, SM_BYTES);
        cudaFuncSetAttribute(gemm_qkv,
                             cudaFuncAttributeMaxDynamicSharedMemorySize, PJ_SMEM_BYTES);
        cudaFuncSetAttribute(gemm_oproj,
                             cudaFuncAttributeMaxDynamicSharedMemorySize, PJ_SMEM_BYTES);
        smem_set = 1;
    }

    // Fused Q/K/V projections (tensor core, 3xTF32) — one launch, 384 CTAs
    gemm_qkv<<<dim3(4, 32, 3), 256, PJ_SMEM_BYTES>>>(
        x, y, q_w, q_b, k_w, k_b, v_w, v_b, Qp, Kp, Vp);

    // K column-sum partials (for mean thresholds)
    ksum_kernel<<<dim3(NG, 8), 256>>>(Kp, KsP);

    // Fused single-pass attention (128 Q rows per CTA)
    attn_fused<<<dim3(SEQ / 128, NG), 256, SM_BYTES>>>(Qp, Kp, Vp, KsP, AO);

    // Output projection (tensor core, 3xTF32)
    gemm_oproj<<<dim3(4, 32), 256, PJ_SMEM_BYTES>>>(AO, o_w, o_b, out);
}

// round 11
// speedup vs baseline: 1.2570x; 1.1006x over previous
#include <cuda_runtime.h>
#include <math.h>
#include <stdint.h>

// Problem constants
#define DM   512
#define SEQ  2048
#define BB   2
#define NH   8
#define HD   64
#define MTOK (BB*SEQ)     // 4096 tokens
#define NG   (NH*BB)      // 16 attention groups

#define NORMF 0.04419417382415922f  // 1/sqrt(512)

// Scratch (static device globals; allocation is forbidden)
__device__ float g_Qp[MTOK * DM];
__device__ float g_Kp[MTOK * DM];
__device__ float g_Vp[MTOK * DM];
__device__ float g_AO[MTOK * DM];
__device__ float g_KsumP[NG * 8 * HD];

// ---------------------------------------------------------------------------
// tf32 mma.sync.m16n8k8 + split helpers
// ---------------------------------------------------------------------------
__device__ __forceinline__ void mma_tf32(float* c, const uint32_t* a, const uint32_t* b)
{
    asm volatile(
        "mma.sync.aligned.m16n8k8.row.col.f32.tf32.tf32.f32 "
        "{%0,%1,%2,%3}, {%4,%5,%6,%7}, {%8,%9}, {%0,%1,%2,%3};\n"
        : "+f"(c[0]), "+f"(c[1]), "+f"(c[2]), "+f"(c[3])
        : "r"(a[0]), "r"(a[1]), "r"(a[2]), "r"(a[3]), "r"(b[0]), "r"(b[1]));
}

__device__ __forceinline__ uint32_t to_tf32(float x)
{
    uint32_t r;
    asm("cvt.rna.tf32.f32 %0, %1;\n" : "=r"(r) : "f"(x));
    return r;
}

__device__ __forceinline__ void split_tf32(float x, float& hi, float& lo)
{
    hi = __uint_as_float(to_tf32(x));
    lo = x - hi;
}

__device__ __forceinline__ void mma3(float* c,
                                     const uint32_t* ah, const uint32_t* al,
                                     const uint32_t* bh, const uint32_t* bl)
{
    mma_tf32(c, ah, bl);
    mma_tf32(c, al, bh);
    mma_tf32(c, ah, bh);
}

// 2-term: C += A_hi*(B_hi + B_lo)  (A already quantized to tf32)
__device__ __forceinline__ void mma2(float* c,
                                     const uint32_t* ah,
                                     const uint32_t* bh, const uint32_t* bl)
{
    mma_tf32(c, ah, bl);
    mma_tf32(c, ah, bh);
}

// ---------------------------------------------------------------------------
// Tensor-core NT projection GEMM body (3xTF32), register-pipelined.
// ---------------------------------------------------------------------------
#define PJ_S 36
#define PJ_SMEM_BYTES (2 * 128 * PJ_S * (int)sizeof(float2))   // 73728

__device__ __forceinline__ void gemm_nt_body(
    const float* __restrict__ A, const float* __restrict__ W,
    const float* __restrict__ bias, float* __restrict__ C,
    float2* sA, float2* sW)
{
    const int tid  = threadIdx.x;
    const int warp = tid >> 5;
    const int lane = tid & 31;
    const int g4   = lane >> 2;
    const int t4   = lane & 3;
    const int wm   = warp >> 2;   // 0..1
    const int wn   = warp & 3;    // 0..3
    const int m0   = blockIdx.y * 128;
    const int n0   = blockIdx.x * 128;

    float acc[4][4][4];
    #pragma unroll
    for (int mf = 0; mf < 4; mf++)
        #pragma unroll
        for (int nf = 0; nf < 4; nf++)
            #pragma unroll
            for (int c = 0; c < 4; c++) acc[mf][nf][c] = 0.f;

    int lr[4], lk[4];
    #pragma unroll
    for (int i = 0; i < 4; i++) {
        int pos = tid + i * 256;
        lr[i] = pos >> 3;
        lk[i] = (pos & 7) << 2;
    }

    float4 ab[4], wb[4];
    #pragma unroll
    for (int i = 0; i < 4; i++) {
        ab[i] = *(const float4*)&A[(size_t)(m0 + lr[i]) * DM + lk[i]];
        wb[i] = *(const float4*)&W[(size_t)(n0 + lr[i]) * DM + lk[i]];
    }

    for (int kt = 0; kt < DM / 32; kt++) {
        __syncthreads();
        #pragma unroll
        for (int i = 0; i < 4; i++) {
            float4 s0, s1;
            split_tf32(ab[i].x, s0.x, s0.y); split_tf32(ab[i].y, s0.z, s0.w);
            split_tf32(ab[i].z, s1.x, s1.y); split_tf32(ab[i].w, s1.z, s1.w);
            *(float4*)&sA[lr[i] * PJ_S + lk[i]]     = s0;
            *(float4*)&sA[lr[i] * PJ_S + lk[i] + 2] = s1;
            split_tf32(wb[i].x, s0.x, s0.y); split_tf32(wb[i].y, s0.z, s0.w);
            split_tf32(wb[i].z, s1.x, s1.y); split_tf32(wb[i].w, s1.z, s1.w);
            *(float4*)&sW[lr[i] * PJ_S + lk[i]]     = s0;
            *(float4*)&sW[lr[i] * PJ_S + lk[i] + 2] = s1;
        }
        __syncthreads();

        if (kt + 1 < DM / 32) {
            const int k0n = (kt + 1) * 32;
            #pragma unroll
            for (int i = 0; i < 4; i++) {
                ab[i] = *(const float4*)&A[(size_t)(m0 + lr[i]) * DM + k0n + lk[i]];
                wb[i] = *(const float4*)&W[(size_t)(n0 + lr[i]) * DM + k0n + lk[i]];
            }
        }

        #pragma unroll
        for (int kk = 0; kk < 4; kk++) {
            const int kc = kk * 8 + t4;
            uint32_t ah[4][4], al[4][4];
            #pragma unroll
            for (int mf = 0; mf < 4; mf++) {
                const int rb = wm * 64 + mf * 16;
                float2 e0 = sA[(rb + g4)     * PJ_S + kc];
                float2 e1 = sA[(rb + g4 + 8) * PJ_S + kc];
                float2 e2 = sA[(rb + g4)     * PJ_S + kc + 4];
                float2 e3 = sA[(rb + g4 + 8) * PJ_S + kc + 4];
                ah[mf][0] = __float_as_uint(e0.x); al[mf][0] = __float_as_uint(e0.y);
                ah[mf][1] = __float_as_uint(e1.x); al[mf][1] = __float_as_uint(e1.y);
                ah[mf][2] = __float_as_uint(e2.x); al[mf][2] = __float_as_uint(e2.y);
                ah[mf][3] = __float_as_uint(e3.x); al[mf][3] = __float_as_uint(e3.y);
            }
            #pragma unroll
            for (int nf = 0; nf < 4; nf++) {
                const int nr = wn * 32 + nf * 8 + g4;
                float2 b0 = sW[nr * PJ_S + kc];
                float2 b1 = sW[nr * PJ_S + kc + 4];
                uint32_t bh[2] = {__float_as_uint(b0.x), __float_as_uint(b1.x)};
                uint32_t bl[2] = {__float_as_uint(b0.y), __float_as_uint(b1.y)};
                #pragma unroll
                for (int mf = 0; mf < 4; mf++)
                    mma3(acc[mf][nf], ah[mf], al[mf], bh, bl);
            }
        }
    }

    #pragma unroll
    for (int nf = 0; nf < 4; nf++) {
        const int col = n0 + wn * 32 + nf * 8 + 2 * t4;
        const float b0 = bias[col], b1 = bias[col + 1];
        #pragma unroll
        for (int mf = 0; mf < 4; mf++) {
            const int r0 = m0 + wm * 64 + mf * 16 + g4;
            *(float2*)&C[(size_t)r0 * DM + col] =
                make_float2(acc[mf][nf][0] + b0, acc[mf][nf][1] + b1);
            *(float2*)&C[(size_t)(r0 + 8) * DM + col] =
                make_float2(acc[mf][nf][2] + b0, acc[mf][nf][3] + b1);
        }
    }
}

// Fused Q/K/V projection: blockIdx.z selects which projection.
__global__ __launch_bounds__(256) void gemm_qkv(
    const float* __restrict__ x, const float* __restrict__ y,
    const float* __restrict__ q_w, const float* __restrict__ q_b,
    const float* __restrict__ k_w, const float* __restrict__ k_b,
    const float* __restrict__ v_w, const float* __restrict__ v_b,
    float* __restrict__ Qp, float* __restrict__ Kp, float* __restrict__ Vp)
{
    extern __shared__ float2 pj_sm[];
    const float *A, *W, *bias;
    float* C;
    if (blockIdx.z == 0)      { A = x; W = q_w; bias = q_b; C = Qp; }
    else if (blockIdx.z == 1) { A = y; W = k_w; bias = k_b; C = Kp; }
    else                      { A = y; W = v_w; bias = v_b; C = Vp; }
    gemm_nt_body(A, W, bias, C, pj_sm, pj_sm + 128 * PJ_S);
}

__global__ __launch_bounds__(256) void gemm_oproj(
    const float* __restrict__ A, const float* __restrict__ W,
    const float* __restrict__ bias, float* __restrict__ C)
{
    extern __shared__ float2 pj_sm[];
    gemm_nt_body(A, W, bias, C, pj_sm, pj_sm + 128 * PJ_S);
}

// ---------------------------------------------------------------------------
// K column-sum partials
// ---------------------------------------------------------------------------
__global__ __launch_bounds__(256) void ksum_kernel(const float* __restrict__ Kp,
                                                   float* __restrict__ out)
{
    const int g  = blockIdx.x;
    const int ch = blockIdx.y;
    const int d  = threadIdx.x & 63;
    const int rc = threadIdx.x >> 6;
    const float* Kg = Kp + ((size_t)g * SEQ + ch * 256) * HD;
    float s = 0.f;
    #pragma unroll 8
    for (int r = rc; r < 256; r += 4) s += Kg[r * HD + d];
    __shared__ float red[256];
    red[threadIdx.x] = s;
    __syncthreads();
    if (rc == 0)
        out[(g * 8 + ch) * HD + d] = red[d] + red[64 + d] + red[128 + d] + red[192 + d];
}

// ---------------------------------------------------------------------------
// Single-pass fused attention, 3xTF32 scores + hi-only P (self-normalized):
// O = (P_hi @ V) / sum(P_hi). CTA = 128 query rows (256 threads, 8 warps).
// K/V (hi,lo)-interleaved float2 stride 68; P hi-only float stride 68.
// ---------------------------------------------------------------------------
#define AT_S 68
#define SM_KV_BYTES (2 * 64 * AT_S * 8)         // K + V float2
#define SM_P_BYTES  (8 * 16 * AT_S * 4)         // P hi floats
#define SM_BYTES (SM_KV_BYTES + SM_P_BYTES)     // 104448 B

__global__ __launch_bounds__(256, 1) void attn_fused(
    const float* __restrict__ Qp, const float* __restrict__ Kp,
    const float* __restrict__ Vp, const float* __restrict__ KsP,
    float* __restrict__ AO)
{
    extern __shared__ float2 sm2[];
    float2* sK2 = sm2;                    // [64][AT_S]
    float2* sV2 = sK2 + 64 * AT_S;        // [64][AT_S]
    float*  sP_all = (float*)(sV2 + 64 * AT_S);   // 8 x [16][AT_S] floats

    const int tid  = threadIdx.x;
    const int warp = tid >> 5;
    const int lane = tid & 31;
    const int g4   = lane >> 2;
    const int t4   = lane & 3;

    const int mt  = blockIdx.x;
    const int grp = blockIdx.y;
    const float* Qg = Qp + (size_t)grp * SEQ * HD;
    const float* Kg = Kp + (size_t)grp * SEQ * HD;
    const float* Vg = Vp + (size_t)grp * SEQ * HD;
    float*       Og = AO + (size_t)grp * SEQ * HD;

    const int m0 = mt * 128;
    const int wrow = warp * 16;           // 0..112
    float* sPf = sP_all + warp * 16 * AT_S;

    // --- Q fragments (registers) + row means via K column-sums ---
    const int row0 = m0 + wrow + g4;
    const int row1 = row0 + 8;
    uint32_t qah[8][4], qal[8][4];
    float mdot0 = 0.f, mdot1 = 0.f;

    #pragma unroll
    for (int kk = 0; kk < 8; kk++) {
        #pragma unroll
        for (int e = 0; e < 2; e++) {
            const int col = kk * 8 + t4 + e * 4;
            float ks = 0.f;
            #pragma unroll
            for (int c = 0; c < 8; c++)
                ks += KsP[(grp * 8 + c) * HD + col];
            float q0 = Qg[(size_t)row0 * HD + col];
            float q1 = Qg[(size_t)row1 * HD + col];
            mdot0 += q0 * ks;
            mdot1 += q1 * ks;
            float h, l;
            split_tf32(q0 * NORMF, h, l);
            qah[kk][e * 2] = __float_as_uint(h);
            qal[kk][e * 2] = __float_as_uint(l);
            split_tf32(q1 * NORMF, h, l);
            qah[kk][e * 2 + 1] = __float_as_uint(h);
            qal[kk][e * 2 + 1] = __float_as_uint(l);
        }
    }
    #pragma unroll
    for (int o = 1; o <= 2; o <<= 1) {
        mdot0 += __shfl_xor_sync(0xffffffffu, mdot0, o);
        mdot1 += __shfl_xor_sync(0xffffffffu, mdot1, o);
    }
    const float mean0 = mdot0 * (NORMF / (float)SEQ);
    const float mean1 = mdot1 * (NORMF / (float)SEQ);

    // --- streaming loop ---
    float oacc[8][4];
    #pragma unroll
    for (int j = 0; j < 8; j++)
        #pragma unroll
        for (int c = 0; c < 4; c++) oacc[j][c] = 0.f;
    float den0 = 0.f, den1 = 0.f;

    for (int kt = 0; kt < SEQ / 64; kt++) {
        __syncthreads();
        // cooperative load + single split of K and V tiles (4 float4/thread)
        #pragma unroll
        for (int i = 0; i < 4; i++) {
            int j = tid + i * 256;
            int r = j >> 4, c4 = (j & 15) << 2;
            float4 kv = *(const float4*)&Kg[(size_t)(kt * 64 + r) * HD + c4];
            float4 vv = *(const float4*)&Vg[(size_t)(kt * 64 + r) * HD + c4];
            float4 s0, s1;
            split_tf32(kv.x, s0.x, s0.y); split_tf32(kv.y, s0.z, s0.w);
            split_tf32(kv.z, s1.x, s1.y); split_tf32(kv.w, s1.z, s1.w);
            *(float4*)&sK2[r * AT_S + c4]     = s0;
            *(float4*)&sK2[r * AT_S + c4 + 2] = s1;
            split_tf32(vv.x, s0.x, s0.y); split_tf32(vv.y, s0.z, s0.w);
            split_tf32(vv.z, s1.x, s1.y); split_tf32(vv.w, s1.z, s1.w);
            *(float4*)&sV2[r * AT_S + c4]     = s0;
            *(float4*)&sV2[r * AT_S + c4 + 2] = s1;
        }
        __syncthreads();

        // S = Qs @ K^T (3xTF32)
        float sacc[8][4];
        #pragma unroll
        for (int j = 0; j < 8; j++)
            #pragma unroll
            for (int c = 0; c < 4; c++) sacc[j][c] = 0.f;

        #pragma unroll
        for (int kk = 0; kk < 8; kk++) {
            const int k0 = kk * 8;
            #pragma unroll
            for (int j = 0; j < 8; j++) {
                const int brow = j * 8 + g4;
                float2 b0 = sK2[brow * AT_S + k0 + t4];
                float2 b1 = sK2[brow * AT_S + k0 + t4 + 4];
                uint32_t bh[2] = {__float_as_uint(b0.x), __float_as_uint(b1.x)};
                uint32_t bl[2] = {__float_as_uint(b0.y), __float_as_uint(b1.y)};
                mma3(sacc[j], qah[kk], qal[kk], bh, bl);
            }
        }

        // mask + exp -> quantize P to tf32-hi; denom from the SAME hi values
        #pragma unroll
        for (int j = 0; j < 8; j++) {
            float p0 = (sacc[j][0] > mean0) ? __expf(sacc[j][0]) : 0.f;
            float p1 = (sacc[j][1] > mean0) ? __expf(sacc[j][1]) : 0.f;
            float p2 = (sacc[j][2] > mean1) ? __expf(sacc[j][2]) : 0.f;
            float p3 = (sacc[j][3] > mean1) ? __expf(sacc[j][3]) : 0.f;
            float h0 = __uint_as_float(to_tf32(p0));
            float h1 = __uint_as_float(to_tf32(p1));
            float h2 = __uint_as_float(to_tf32(p2));
            float h3 = __uint_as_float(to_tf32(p3));
            den0 += h0 + h1;
            den1 += h2 + h3;
            *(float2*)&sPf[g4       * AT_S + j * 8 + 2 * t4] = make_float2(h0, h1);
            *(float2*)&sPf[(g4 + 8) * AT_S + j * 8 + 2 * t4] = make_float2(h2, h3);
        }
        __syncwarp();

        // O += P_hi @ (V_hi + V_lo)  (2 mma per step)
        #pragma unroll
        for (int kk = 0; kk < 8; kk++) {
            const int k0 = kk * 8;
            uint32_t ah[4];
            ah[0] = __float_as_uint(sPf[g4       * AT_S + k0 + t4]);
            ah[1] = __float_as_uint(sPf[(g4 + 8) * AT_S + k0 + t4]);
            ah[2] = __float_as_uint(sPf[g4       * AT_S + k0 + t4 + 4]);
            ah[3] = __float_as_uint(sPf[(g4 + 8) * AT_S + k0 + t4 + 4]);
            #pragma unroll
            for (int j = 0; j < 8; j++) {
                const int bcol = j * 8 + g4;
                float2 b0 = sV2[(k0 + t4)     * AT_S + bcol];
                float2 b1 = sV2[(k0 + t4 + 4) * AT_S + bcol];
                uint32_t bh[2] = {__float_as_uint(b0.x), __float_as_uint(b1.x)};
                uint32_t bl[2] = {__float_as_uint(b0.y), __float_as_uint(b1.y)};
                mma2(oacc[j], ah, bh, bl);
            }
        }
    }

    // reduce denominators, normalize, write out
    #pragma unroll
    for (int o = 1; o <= 2; o <<= 1) {
        den0 += __shfl_xor_sync(0xffffffffu, den0, o);
        den1 += __shfl_xor_sync(0xffffffffu, den1, o);
    }
    const float inv0 = 1.f / den0;
    const float inv1 = 1.f / den1;

    #pragma unroll
    for (int j = 0; j < 8; j++) {
        const int col = j * 8 + 2 * t4;
        *(float2*)&Og[(size_t)row0 * HD + col] =
            make_float2(oacc[j][0] * inv0, oacc[j][1] * inv0);
        *(float2*)&Og[(size_t)row1 * HD + col] =
            make_float2(oacc[j][2] * inv1, oacc[j][3] * inv1);
    }
}

// ---------------------------------------------------------------------------
// Launch
// ---------------------------------------------------------------------------
extern "C" void kernel_launch(void* const* d_in, const int* in_sizes, int n_in,
                              void* d_out, int out_size)
{
    const float* x   = (const float*)d_in[0];
    const float* y   = (const float*)d_in[1];
    const float* q_w = (const float*)d_in[2];
    const float* q_b = (const float*)d_in[3];
    const float* k_w = (const float*)d_in[4];
    const float* k_b = (const float*)d_in[5];
    const float* v_w = (const float*)d_in[6];
    const float* v_b = (const float*)d_in[7];
    const float* o_w = (const float*)d_in[8];
    const float* o_b = (const float*)d_in[9];
    float* out = (float*)d_out;

    float *Qp, *Kp, *Vp, *AO, *KsP;
    cudaGetSymbolAddress((void**)&Qp, g_Qp);
    cudaGetSymbolAddress((void**)&Kp, g_Kp);
    cudaGetSymbolAddress((void**)&Vp, g_Vp);
    cudaGetSymbolAddress((void**)&AO, g_AO);
    cudaGetSymbolAddress((void**)&KsP, g_KsumP);

    static int smem_set = 0;
    if (!smem_set) {
        cudaFuncSetAttribute(attn_fused,
                             cudaFuncAttributeMaxDynamicSharedMemorySize, SM_BYTES);
        cudaFuncSetAttribute(gemm_qkv,
                             cudaFuncAttributeMaxDynamicSharedMemorySize, PJ_SMEM_BYTES);
        cudaFuncSetAttribute(gemm_oproj,
                             cudaFuncAttributeMaxDynamicSharedMemorySize, PJ_SMEM_BYTES);
        smem_set = 1;
    }

    // Fused Q/K/V projections (tensor core, 3xTF32) — one launch, 384 CTAs
    gemm_qkv<<<dim3(4, 32, 3), 256, PJ_SMEM_BYTES>>>(
        x, y, q_w, q_b, k_w, k_b, v_w, v_b, Qp, Kp, Vp);

    // K column-sum partials (for mean thresholds)
    ksum_kernel<<<dim3(NG, 8), 256>>>(Kp, KsP);

    // Fused single-pass attention (128 Q rows per CTA)
    attn_fused<<<dim3(SEQ / 128, NG), 256, SM_BYTES>>>(Qp, Kp, Vp, KsP, AO);

    // Output projection (tensor core, 3xTF32)
    gemm_oproj<<<dim3(4, 32), 256, PJ_SMEM_BYTES>>>(AO, o_w, o_b, out);
}

// round 12
// speedup vs baseline: 1.3606x; 1.0825x over previous
#include <cuda_runtime.h>
#include <math.h>
#include <stdint.h>

// Problem constants
#define DM   512
#define SEQ  2048
#define BB   2
#define NH   8
#define HD   64
#define MTOK (BB*SEQ)     // 4096 tokens
#define NG   (NH*BB)      // 16 attention groups

#define NORMF 0.04419417382415922f  // 1/sqrt(512)

// Scratch (static device globals; allocation is forbidden)
__device__ float g_Qp[MTOK * DM];
__device__ float g_Kp[MTOK * DM];
__device__ float g_Vp[MTOK * DM];
__device__ float g_AO[MTOK * DM];
__device__ float g_KsumP[NG * 8 * HD];

// ---------------------------------------------------------------------------
// tf32 mma.sync.m16n8k8 + split helpers
// ---------------------------------------------------------------------------
__device__ __forceinline__ void mma_tf32(float* c, const uint32_t* a, const uint32_t* b)
{
    asm volatile(
        "mma.sync.aligned.m16n8k8.row.col.f32.tf32.tf32.f32 "
        "{%0,%1,%2,%3}, {%4,%5,%6,%7}, {%8,%9}, {%0,%1,%2,%3};\n"
        : "+f"(c[0]), "+f"(c[1]), "+f"(c[2]), "+f"(c[3])
        : "r"(a[0]), "r"(a[1]), "r"(a[2]), "r"(a[3]), "r"(b[0]), "r"(b[1]));
}

__device__ __forceinline__ uint32_t to_tf32(float x)
{
    uint32_t r;
    asm("cvt.rna.tf32.f32 %0, %1;\n" : "=r"(r) : "f"(x));
    return r;
}

__device__ __forceinline__ void split_tf32(float x, float& hi, float& lo)
{
    hi = __uint_as_float(to_tf32(x));
    lo = x - hi;
}

__device__ __forceinline__ void mma3(float* c,
                                     const uint32_t* ah, const uint32_t* al,
                                     const uint32_t* bh, const uint32_t* bl)
{
    mma_tf32(c, ah, bl);
    mma_tf32(c, al, bh);
    mma_tf32(c, ah, bh);
}

// ---------------------------------------------------------------------------
// Tensor-core NT projection GEMM body (3xTF32), register-pipelined.
// ---------------------------------------------------------------------------
#define PJ_S 36
#define PJ_SMEM_BYTES (2 * 128 * PJ_S * (int)sizeof(float2))   // 73728

__device__ __forceinline__ void gemm_nt_body(
    const float* __restrict__ A, const float* __restrict__ W,
    const float* __restrict__ bias, float* __restrict__ C,
    float2* sA, float2* sW)
{
    const int tid  = threadIdx.x;
    const int warp = tid >> 5;
    const int lane = tid & 31;
    const int g4   = lane >> 2;
    const int t4   = lane & 3;
    const int wm   = warp >> 2;   // 0..1
    const int wn   = warp & 3;    // 0..3
    const int m0   = blockIdx.y * 128;
    const int n0   = blockIdx.x * 128;

    float acc[4][4][4];
    #pragma unroll
    for (int mf = 0; mf < 4; mf++)
        #pragma unroll
        for (int nf = 0; nf < 4; nf++)
            #pragma unroll
            for (int c = 0; c < 4; c++) acc[mf][nf][c] = 0.f;

    int lr[4], lk[4];
    #pragma unroll
    for (int i = 0; i < 4; i++) {
        int pos = tid + i * 256;
        lr[i] = pos >> 3;
        lk[i] = (pos & 7) << 2;
    }

    float4 ab[4], wb[4];
    #pragma unroll
    for (int i = 0; i < 4; i++) {
        ab[i] = *(const float4*)&A[(size_t)(m0 + lr[i]) * DM + lk[i]];
        wb[i] = *(const float4*)&W[(size_t)(n0 + lr[i]) * DM + lk[i]];
    }

    for (int kt = 0; kt < DM / 32; kt++) {
        __syncthreads();
        #pragma unroll
        for (int i = 0; i < 4; i++) {
            float4 s0, s1;
            split_tf32(ab[i].x, s0.x, s0.y); split_tf32(ab[i].y, s0.z, s0.w);
            split_tf32(ab[i].z, s1.x, s1.y); split_tf32(ab[i].w, s1.z, s1.w);
            *(float4*)&sA[lr[i] * PJ_S + lk[i]]     = s0;
            *(float4*)&sA[lr[i] * PJ_S + lk[i] + 2] = s1;
            split_tf32(wb[i].x, s0.x, s0.y); split_tf32(wb[i].y, s0.z, s0.w);
            split_tf32(wb[i].z, s1.x, s1.y); split_tf32(wb[i].w, s1.z, s1.w);
            *(float4*)&sW[lr[i] * PJ_S + lk[i]]     = s0;
            *(float4*)&sW[lr[i] * PJ_S + lk[i] + 2] = s1;
        }
        __syncthreads();

        if (kt + 1 < DM / 32) {
            const int k0n = (kt + 1) * 32;
            #pragma unroll
            for (int i = 0; i < 4; i++) {
                ab[i] = *(const float4*)&A[(size_t)(m0 + lr[i]) * DM + k0n + lk[i]];
                wb[i] = *(const float4*)&W[(size_t)(n0 + lr[i]) * DM + k0n + lk[i]];
            }
        }

        #pragma unroll
        for (int kk = 0; kk < 4; kk++) {
            const int kc = kk * 8 + t4;
            uint32_t ah[4][4], al[4][4];
            #pragma unroll
            for (int mf = 0; mf < 4; mf++) {
                const int rb = wm * 64 + mf * 16;
                float2 e0 = sA[(rb + g4)     * PJ_S + kc];
                float2 e1 = sA[(rb + g4 + 8) * PJ_S + kc];
                float2 e2 = sA[(rb + g4)     * PJ_S + kc + 4];
                float2 e3 = sA[(rb + g4 + 8) * PJ_S + kc + 4];
                ah[mf][0] = __float_as_uint(e0.x); al[mf][0] = __float_as_uint(e0.y);
                ah[mf][1] = __float_as_uint(e1.x); al[mf][1] = __float_as_uint(e1.y);
                ah[mf][2] = __float_as_uint(e2.x); al[mf][2] = __float_as_uint(e2.y);
                ah[mf][3] = __float_as_uint(e3.x); al[mf][3] = __float_as_uint(e3.y);
            }
            #pragma unroll
            for (int nf = 0; nf < 4; nf++) {
                const int nr = wn * 32 + nf * 8 + g4;
                float2 b0 = sW[nr * PJ_S + kc];
                float2 b1 = sW[nr * PJ_S + kc + 4];
                uint32_t bh[2] = {__float_as_uint(b0.x), __float_as_uint(b1.x)};
                uint32_t bl[2] = {__float_as_uint(b0.y), __float_as_uint(b1.y)};
                #pragma unroll
                for (int mf = 0; mf < 4; mf++)
                    mma3(acc[mf][nf], ah[mf], al[mf], bh, bl);
            }
        }
    }

    #pragma unroll
    for (int nf = 0; nf < 4; nf++) {
        const int col = n0 + wn * 32 + nf * 8 + 2 * t4;
        const float b0 = bias[col], b1 = bias[col + 1];
        #pragma unroll
        for (int mf = 0; mf < 4; mf++) {
            const int r0 = m0 + wm * 64 + mf * 16 + g4;
            *(float2*)&C[(size_t)r0 * DM + col] =
                make_float2(acc[mf][nf][0] + b0, acc[mf][nf][1] + b1);
            *(float2*)&C[(size_t)(r0 + 8) * DM + col] =
                make_float2(acc[mf][nf][2] + b0, acc[mf][nf][3] + b1);
        }
    }
}

// Fused Q/K/V projection: blockIdx.z selects which projection.
__global__ __launch_bounds__(256) void gemm_qkv(
    const float* __restrict__ x, const float* __restrict__ y,
    const float* __restrict__ q_w, const float* __restrict__ q_b,
    const float* __restrict__ k_w, const float* __restrict__ k_b,
    const float* __restrict__ v_w, const float* __restrict__ v_b,
    float* __restrict__ Qp, float* __restrict__ Kp, float* __restrict__ Vp)
{
    extern __shared__ float2 pj_sm[];
    const float *A, *W, *bias;
    float* C;
    if (blockIdx.z == 0)      { A = x; W = q_w; bias = q_b; C = Qp; }
    else if (blockIdx.z == 1) { A = y; W = k_w; bias = k_b; C = Kp; }
    else                      { A = y; W = v_w; bias = v_b; C = Vp; }
    gemm_nt_body(A, W, bias, C, pj_sm, pj_sm + 128 * PJ_S);
}

__global__ __launch_bounds__(256) void gemm_oproj(
    const float* __restrict__ A, const float* __restrict__ W,
    const float* __restrict__ bias, float* __restrict__ C)
{
    extern __shared__ float2 pj_sm[];
    gemm_nt_body(A, W, bias, C, pj_sm, pj_sm + 128 * PJ_S);
}

// ---------------------------------------------------------------------------
// K column-sum partials
// ---------------------------------------------------------------------------
__global__ __launch_bounds__(256) void ksum_kernel(const float* __restrict__ Kp,
                                                   float* __restrict__ out)
{
    const int g  = blockIdx.x;
    const int ch = blockIdx.y;
    const int d  = threadIdx.x & 63;
    const int rc = threadIdx.x >> 6;
    const float* Kg = Kp + ((size_t)g * SEQ + ch * 256) * HD;
    float s = 0.f;
    #pragma unroll 8
    for (int r = rc; r < 256; r += 4) s += Kg[r * HD + d];
    __shared__ float red[256];
    red[threadIdx.x] = s;
    __syncthreads();
    if (rc == 0)
        out[(g * 8 + ch) * HD + d] = red[d] + red[64 + d] + red[128 + d] + red[192 + d];
}

// ---------------------------------------------------------------------------
// Single-pass fused attention:
//   scores: 3xTF32 (full precision — mask decisions are fragile)
//   P:      tf32-hi only, self-normalized (O = P_hi@V_hi / sum(P_hi))
//   V:      tf32-hi only (incoherent quantization noise ~2^-12)
// CTA = 128 query rows (256 threads, 8 warps x 16 rows).
// K (hi,lo) float2 stride 68; V hi float stride 72 (banks g4+8*t4 distinct);
// P hi float stride 68.
// ---------------------------------------------------------------------------
#define AT_S  68
#define AT_SV 72
#define SM_K_BYTES (64 * AT_S * 8)              // K float2
#define SM_V_BYTES (64 * AT_SV * 4)             // V hi floats
#define SM_P_BYTES (8 * 16 * AT_S * 4)          // P hi floats
#define SM_BYTES (SM_K_BYTES + SM_V_BYTES + SM_P_BYTES)   // 88064 B

__global__ __launch_bounds__(256, 1) void attn_fused(
    const float* __restrict__ Qp, const float* __restrict__ Kp,
    const float* __restrict__ Vp, const float* __restrict__ KsP,
    float* __restrict__ AO)
{
    extern __shared__ float2 sm2[];
    float2* sK2 = sm2;                                // [64][AT_S]
    float*  sVf = (float*)(sK2 + 64 * AT_S);          // [64][AT_SV]
    float*  sP_all = sVf + 64 * AT_SV;                // 8 x [16][AT_S]

    const int tid  = threadIdx.x;
    const int warp = tid >> 5;
    const int lane = tid & 31;
    const int g4   = lane >> 2;
    const int t4   = lane & 3;

    const int mt  = blockIdx.x;
    const int grp = blockIdx.y;
    const float* Qg = Qp + (size_t)grp * SEQ * HD;
    const float* Kg = Kp + (size_t)grp * SEQ * HD;
    const float* Vg = Vp + (size_t)grp * SEQ * HD;
    float*       Og = AO + (size_t)grp * SEQ * HD;

    const int m0 = mt * 128;
    const int wrow = warp * 16;           // 0..112
    float* sPf = sP_all + warp * 16 * AT_S;

    // --- Q fragments (registers) + row means via K column-sums ---
    const int row0 = m0 + wrow + g4;
    const int row1 = row0 + 8;
    uint32_t qah[8][4], qal[8][4];
    float mdot0 = 0.f, mdot1 = 0.f;

    #pragma unroll
    for (int kk = 0; kk < 8; kk++) {
        #pragma unroll
        for (int e = 0; e < 2; e++) {
            const int col = kk * 8 + t4 + e * 4;
            float ks = 0.f;
            #pragma unroll
            for (int c = 0; c < 8; c++)
                ks += KsP[(grp * 8 + c) * HD + col];
            float q0 = Qg[(size_t)row0 * HD + col];
            float q1 = Qg[(size_t)row1 * HD + col];
            mdot0 += q0 * ks;
            mdot1 += q1 * ks;
            float h, l;
            split_tf32(q0 * NORMF, h, l);
            qah[kk][e * 2] = __float_as_uint(h);
            qal[kk][e * 2] = __float_as_uint(l);
            split_tf32(q1 * NORMF, h, l);
            qah[kk][e * 2 + 1] = __float_as_uint(h);
            qal[kk][e * 2 + 1] = __float_as_uint(l);
        }
    }
    #pragma unroll
    for (int o = 1; o <= 2; o <<= 1) {
        mdot0 += __shfl_xor_sync(0xffffffffu, mdot0, o);
        mdot1 += __shfl_xor_sync(0xffffffffu, mdot1, o);
    }
    const float mean0 = mdot0 * (NORMF / (float)SEQ);
    const float mean1 = mdot1 * (NORMF / (float)SEQ);

    // --- streaming loop ---
    float oacc[8][4];
    #pragma unroll
    for (int j = 0; j < 8; j++)
        #pragma unroll
        for (int c = 0; c < 4; c++) oacc[j][c] = 0.f;
    float den0 = 0.f, den1 = 0.f;

    for (int kt = 0; kt < SEQ / 64; kt++) {
        __syncthreads();
        // cooperative load: split K to (hi,lo); quantize V to hi-only
        #pragma unroll
        for (int i = 0; i < 4; i++) {
            int j = tid + i * 256;
            int r = j >> 4, c4 = (j & 15) << 2;
            float4 kv = *(const float4*)&Kg[(size_t)(kt * 64 + r) * HD + c4];
            float4 vv = *(const float4*)&Vg[(size_t)(kt * 64 + r) * HD + c4];
            float4 s0, s1;
            split_tf32(kv.x, s0.x, s0.y); split_tf32(kv.y, s0.z, s0.w);
            split_tf32(kv.z, s1.x, s1.y); split_tf32(kv.w, s1.z, s1.w);
            *(float4*)&sK2[r * AT_S + c4]     = s0;
            *(float4*)&sK2[r * AT_S + c4 + 2] = s1;
            float4 vh;
            vh.x = __uint_as_float(to_tf32(vv.x));
            vh.y = __uint_as_float(to_tf32(vv.y));
            vh.z = __uint_as_float(to_tf32(vv.z));
            vh.w = __uint_as_float(to_tf32(vv.w));
            *(float4*)&sVf[r * AT_SV + c4] = vh;
        }
        __syncthreads();

        // S = Qs @ K^T (3xTF32)
        float sacc[8][4];
        #pragma unroll
        for (int j = 0; j < 8; j++)
            #pragma unroll
            for (int c = 0; c < 4; c++) sacc[j][c] = 0.f;

        #pragma unroll
        for (int kk = 0; kk < 8; kk++) {
            const int k0 = kk * 8;
            #pragma unroll
            for (int j = 0; j < 8; j++) {
                const int brow = j * 8 + g4;
                float2 b0 = sK2[brow * AT_S + k0 + t4];
                float2 b1 = sK2[brow * AT_S + k0 + t4 + 4];
                uint32_t bh[2] = {__float_as_uint(b0.x), __float_as_uint(b1.x)};
                uint32_t bl[2] = {__float_as_uint(b0.y), __float_as_uint(b1.y)};
                mma3(sacc[j], qah[kk], qal[kk], bh, bl);
            }
        }

        // mask + exp -> quantize P to tf32-hi; denom from the SAME hi values
        #pragma unroll
        for (int j = 0; j < 8; j++) {
            float p0 = (sacc[j][0] > mean0) ? __expf(sacc[j][0]) : 0.f;
            float p1 = (sacc[j][1] > mean0) ? __expf(sacc[j][1]) : 0.f;
            float p2 = (sacc[j][2] > mean1) ? __expf(sacc[j][2]) : 0.f;
            float p3 = (sacc[j][3] > mean1) ? __expf(sacc[j][3]) : 0.f;
            float h0 = __uint_as_float(to_tf32(p0));
            float h1 = __uint_as_float(to_tf32(p1));
            float h2 = __uint_as_float(to_tf32(p2));
            float h3 = __uint_as_float(to_tf32(p3));
            den0 += h0 + h1;
            den1 += h2 + h3;
            *(float2*)&sPf[g4       * AT_S + j * 8 + 2 * t4] = make_float2(h0, h1);
            *(float2*)&sPf[(g4 + 8) * AT_S + j * 8 + 2 * t4] = make_float2(h2, h3);
        }
        __syncwarp();

        // O += P_hi @ V_hi  (1 mma per step)
        #pragma unroll
        for (int kk = 0; kk < 8; kk++) {
            const int k0 = kk * 8;
            uint32_t ah[4];
            ah[0] = __float_as_uint(sPf[g4       * AT_S + k0 + t4]);
            ah[1] = __float_as_uint(sPf[(g4 + 8) * AT_S + k0 + t4]);
            ah[2] = __float_as_uint(sPf[g4       * AT_S + k0 + t4 + 4]);
            ah[3] = __float_as_uint(sPf[(g4 + 8) * AT_S + k0 + t4 + 4]);
            #pragma unroll
            for (int j = 0; j < 8; j++) {
                const int bcol = j * 8 + g4;
                uint32_t bh[2];
                bh[0] = __float_as_uint(sVf[(k0 + t4)     * AT_SV + bcol]);
                bh[1] = __float_as_uint(sVf[(k0 + t4 + 4) * AT_SV + bcol]);
                mma_tf32(oacc[j], ah, bh);
            }
        }
    }

    // reduce denominators, normalize, write out
    #pragma unroll
    for (int o = 1; o <= 2; o <<= 1) {
        den0 += __shfl_xor_sync(0xffffffffu, den0, o);
        den1 += __shfl_xor_sync(0xffffffffu, den1, o);
    }
    const float inv0 = 1.f / den0;
    const float inv1 = 1.f / den1;

    #pragma unroll
    for (int j = 0; j < 8; j++) {
        const int col = j * 8 + 2 * t4;
        *(float2*)&Og[(size_t)row0 * HD + col] =
            make_float2(oacc[j][0] * inv0, oacc[j][1] * inv0);
        *(float2*)&Og[(size_t)row1 * HD + col] =
            make_float2(oacc[j][2] * inv1, oacc[j][3] * inv1);
    }
}

// ---------------------------------------------------------------------------
// Launch
// ---------------------------------------------------------------------------
extern "C" void kernel_launch(void* const* d_in, const int* in_sizes, int n_in,
                              void* d_out, int out_size)
{
    const float* x   = (const float*)d_in[0];
    const float* y   = (const float*)d_in[1];
    const float* q_w = (const float*)d_in[2];
    const float* q_b = (const float*)d_in[3];
    const float* k_w = (const float*)d_in[4];
    const float* k_b = (const float*)d_in[5];
    const float* v_w = (const float*)d_in[6];
    const float* v_b = (const float*)d_in[7];
    const float* o_w = (const float*)d_in[8];
    const float* o_b = (const float*)d_in[9];
    float* out = (float*)d_out;

    float *Qp, *Kp, *Vp, *AO, *KsP;
    cudaGetSymbolAddress((void**)&Qp, g_Qp);
    cudaGetSymbolAddress((void**)&Kp, g_Kp);
    cudaGetSymbolAddress((void**)&Vp, g_Vp);
    cudaGetSymbolAddress((void**)&AO, g_AO);
    cudaGetSymbolAddress((void**)&KsP, g_KsumP);

    static int smem_set = 0;
    if (!smem_set) {
        cudaFuncSetAttribute(attn_fused,
                             cudaFuncAttributeMaxDynamicSharedMemorySize, SM_BYTES);
        cudaFuncSetAttribute(gemm_qkv,
                             cudaFuncAttributeMaxDynamicSharedMemorySize, PJ_SMEM_BYTES);
        cudaFuncSetAttribute(gemm_oproj,
                             cudaFuncAttributeMaxDynamicSharedMemorySize, PJ_SMEM_BYTES);
        smem_set = 1;
    }

    // Fused Q/K/V projections (tensor core, 3xTF32) — one launch, 384 CTAs
    gemm_qkv<<<dim3(4, 32, 3), 256, PJ_SMEM_BYTES>>>(
        x, y, q_w, q_b, k_w, k_b, v_w, v_b, Qp, Kp, Vp);

    // K column-sum partials (for mean thresholds)
    ksum_kernel<<<dim3(NG, 8), 256>>>(Kp, KsP);

    // Fused single-pass attention (128 Q rows per CTA)
    attn_fused<<<dim3(SEQ / 128, NG), 256, SM_BYTES>>>(Qp, Kp, Vp, KsP, AO);

    // Output projection (tensor core, 3xTF32)
    gemm_oproj<<<dim3(4, 32), 256, PJ_SMEM_BYTES>>>(AO, o_w, o_b, out);
}

// round 14
// speedup vs baseline: 1.9080x; 1.4023x over previous
#include <cuda_runtime.h>
#include <cuda_bf16.h>
#include <math.h>
#include <stdint.h>

// Problem constants
#define DM   512
#define SEQ  2048
#define BB   2
#define NH   8
#define HD   64
#define MTOK (BB*SEQ)     // 4096 tokens
#define NG   (NH*BB)      // 16 attention groups

#define NORMF 0.04419417382415922f  // 1/sqrt(512)

// Scratch (static device globals; allocation is forbidden)
__device__ float g_Qp[MTOK * DM];
__device__ float g_Kp[MTOK * DM];
__device__ float g_Vp[MTOK * DM];
__device__ float g_AO[MTOK * DM];
__device__ float g_KsumP[NG * 8 * HD];

// ---------------------------------------------------------------------------
// mma wrappers + split helpers
// ---------------------------------------------------------------------------
__device__ __forceinline__ void mma_tf32(float* c, const uint32_t* a, const uint32_t* b)
{
    asm volatile(
        "mma.sync.aligned.m16n8k8.row.col.f32.tf32.tf32.f32 "
        "{%0,%1,%2,%3}, {%4,%5,%6,%7}, {%8,%9}, {%0,%1,%2,%3};\n"
        : "+f"(c[0]), "+f"(c[1]), "+f"(c[2]), "+f"(c[3])
        : "r"(a[0]), "r"(a[1]), "r"(a[2]), "r"(a[3]), "r"(b[0]), "r"(b[1]));
}

__device__ __forceinline__ void mma_bf16(float* c, const uint32_t* a, const uint32_t* b)
{
    asm volatile(
        "mma.sync.aligned.m16n8k16.row.col.f32.bf16.bf16.f32 "
        "{%0,%1,%2,%3}, {%4,%5,%6,%7}, {%8,%9}, {%0,%1,%2,%3};\n"
        : "+f"(c[0]), "+f"(c[1]), "+f"(c[2]), "+f"(c[3])
        : "r"(a[0]), "r"(a[1]), "r"(a[2]), "r"(a[3]), "r"(b[0]), "r"(b[1]));
}

__device__ __forceinline__ uint32_t to_tf32(float x)
{
    uint32_t r;
    asm("cvt.rna.tf32.f32 %0, %1;\n" : "=r"(r) : "f"(x));
    return r;
}

__device__ __forceinline__ void split_tf32(float x, float& hi, float& lo)
{
    hi = __uint_as_float(to_tf32(x));
    lo = x - hi;
}

__device__ __forceinline__ void mma3(float* c,
                                     const uint32_t* ah, const uint32_t* al,
                                     const uint32_t* bh, const uint32_t* bl)
{
    mma_tf32(c, ah, bl);
    mma_tf32(c, al, bh);
    mma_tf32(c, ah, bh);
}

__device__ __forceinline__ void mma3_bf16(float* c,
                                          const uint32_t* ah, const uint32_t* al,
                                          const uint32_t* bh, const uint32_t* bl)
{
    mma_bf16(c, ah, bl);
    mma_bf16(c, al, bh);
    mma_bf16(c, ah, bh);
}

// pack 2 floats into bf16x2 (lower half = f0)
__device__ __forceinline__ uint32_t bf16x2(float f0, float f1)
{
    uint32_t r;
    asm("cvt.rn.bf16x2.f32 %0, %1, %2;\n" : "=r"(r) : "f"(f1), "f"(f0));
    return r;
}

// split pair (f0,f1) into bf16x2 hi + bf16x2 lo planes
__device__ __forceinline__ void split_bf16x2(float f0, float f1,
                                             uint32_t& hp, uint32_t& lp)
{
    hp = bf16x2(f0, f1);
    float h0 = __uint_as_float(hp << 16);
    float h1 = __uint_as_float(hp & 0xFFFF0000u);
    lp = bf16x2(f0 - h0, f1 - h1);
}

// ---------------------------------------------------------------------------
// 3xBF16 NT projection GEMM: C[4096,512] = A @ W^T + bias
// 128x128 CTA tile, BK=32 (2 k-steps of 16), 8 warps (2m x 4n), warp 64x32.
// SMEM: hi/lo bf16x2 planes, row stride 20 uint32 (banks 20*g4+t4 distinct).
// Register-pipelined global loads (32-reg buffer).
// ---------------------------------------------------------------------------
#define BQ_S 20

__device__ __forceinline__ void gemm_bf16_body(
    const float* __restrict__ A, const float* __restrict__ W,
    const float* __restrict__ bias, float* __restrict__ C)
{
    __shared__ uint32_t sAh[128 * BQ_S], sAl[128 * BQ_S];
    __shared__ uint32_t sWh[128 * BQ_S], sWl[128 * BQ_S];

    const int tid  = threadIdx.x;
    const int warp = tid >> 5;
    const int lane = tid & 31;
    const int g4   = lane >> 2;
    const int t4   = lane & 3;
    const int wm   = warp >> 2;   // 0..1
    const int wn   = warp & 3;    // 0..3
    const int m0   = blockIdx.y * 128;
    const int n0   = blockIdx.x * 128;

    float acc[4][4][4];
    #pragma unroll
    for (int mf = 0; mf < 4; mf++)
        #pragma unroll
        for (int nf = 0; nf < 4; nf++)
            #pragma unroll
            for (int c = 0; c < 4; c++) acc[mf][nf][c] = 0.f;

    int lr[4], lk[4];
    #pragma unroll
    for (int i = 0; i < 4; i++) {
        int pos = tid + i * 256;          // 0..1023
        lr[i] = pos >> 3;                 // row 0..127
        lk[i] = (pos & 7) << 2;           // col 0..28 step 4
    }

    float4 ab[4], wb[4];
    #pragma unroll
    for (int i = 0; i < 4; i++) {
        ab[i] = *(const float4*)&A[(size_t)(m0 + lr[i]) * DM + lk[i]];
        wb[i] = *(const float4*)&W[(size_t)(n0 + lr[i]) * DM + lk[i]];
    }

    for (int kt = 0; kt < DM / 32; kt++) {
        __syncthreads();
        #pragma unroll
        for (int i = 0; i < 4; i++) {
            uint32_t h0, l0, h1, l1;
            const int idx = lr[i] * BQ_S + (lk[i] >> 1);
            split_bf16x2(ab[i].x, ab[i].y, h0, l0);
            split_bf16x2(ab[i].z, ab[i].w, h1, l1);
            sAh[idx] = h0; sAh[idx + 1] = h1;
            sAl[idx] = l0; sAl[idx + 1] = l1;
            split_bf16x2(wb[i].x, wb[i].y, h0, l0);
            split_bf16x2(wb[i].z, wb[i].w, h1, l1);
            sWh[idx] = h0; sWh[idx + 1] = h1;
            sWl[idx] = l0; sWl[idx + 1] = l1;
        }
        __syncthreads();

        if (kt + 1 < DM / 32) {
            const int k0n = (kt + 1) * 32;
            #pragma unroll
            for (int i = 0; i < 4; i++) {
                ab[i] = *(const float4*)&A[(size_t)(m0 + lr[i]) * DM + k0n + lk[i]];
                wb[i] = *(const float4*)&W[(size_t)(n0 + lr[i]) * DM + k0n + lk[i]];
            }
        }

        #pragma unroll
        for (int ks = 0; ks < 2; ks++) {
            const int cb = ks * 8 + t4;
            uint32_t ah[4][4], al[4][4];
            #pragma unroll
            for (int mf = 0; mf < 4; mf++) {
                const int rb = wm * 64 + mf * 16;
                ah[mf][0] = sAh[(rb + g4)     * BQ_S + cb];
                ah[mf][1] = sAh[(rb + g4 + 8) * BQ_S + cb];
                ah[mf][2] = sAh[(rb + g4)     * BQ_S + cb + 4];
                ah[mf][3] = sAh[(rb + g4 + 8) * BQ_S + cb + 4];
                al[mf][0] = sAl[(rb + g4)     * BQ_S + cb];
                al[mf][1] = sAl[(rb + g4 + 8) * BQ_S + cb];
                al[mf][2] = sAl[(rb + g4)     * BQ_S + cb + 4];
                al[mf][3] = sAl[(rb + g4 + 8) * BQ_S + cb + 4];
            }
            #pragma unroll
            for (int nf = 0; nf < 4; nf++) {
                const int nr = wn * 32 + nf * 8 + g4;
                uint32_t bh[2], bl[2];
                bh[0] = sWh[nr * BQ_S + cb];
                bh[1] = sWh[nr * BQ_S + cb + 4];
                bl[0] = sWl[nr * BQ_S + cb];
                bl[1] = sWl[nr * BQ_S + cb + 4];
                #pragma unroll
                for (int mf = 0; mf < 4; mf++)
                    mma3_bf16(acc[mf][nf], ah[mf], al[mf], bh, bl);
            }
        }
    }

    #pragma unroll
    for (int nf = 0; nf < 4; nf++) {
        const int col = n0 + wn * 32 + nf * 8 + 2 * t4;
        const float b0 = bias[col], b1 = bias[col + 1];
        #pragma unroll
        for (int mf = 0; mf < 4; mf++) {
            const int r0 = m0 + wm * 64 + mf * 16 + g4;
            *(float2*)&C[(size_t)r0 * DM + col] =
                make_float2(acc[mf][nf][0] + b0, acc[mf][nf][1] + b1);
            *(float2*)&C[(size_t)(r0 + 8) * DM + col] =
                make_float2(acc[mf][nf][2] + b0, acc[mf][nf][3] + b1);
        }
    }
}

// Fused Q/K/V projection: blockIdx.z selects which projection.
__global__ __launch_bounds__(256) void gemm_qkv(
    const float* __restrict__ x, const float* __restrict__ y,
    const float* __restrict__ q_w, const float* __restrict__ q_b,
    const float* __restrict__ k_w, const float* __restrict__ k_b,
    const float* __restrict__ v_w, const float* __restrict__ v_b,
    float* __restrict__ Qp, float* __restrict__ Kp, float* __restrict__ Vp)
{
    const float *A, *W, *bias;
    float* C;
    if (blockIdx.z == 0)      { A = x; W = q_w; bias = q_b; C = Qp; }
    else if (blockIdx.z == 1) { A = y; W = k_w; bias = k_b; C = Kp; }
    else                      { A = y; W = v_w; bias = v_b; C = Vp; }
    gemm_bf16_body(A, W, bias, C);
}

__global__ __launch_bounds__(256) void gemm_oproj(
    const float* __restrict__ A, const float* __restrict__ W,
    const float* __restrict__ bias, float* __restrict__ C)
{
    gemm_bf16_body(A, W, bias, C);
}

// ---------------------------------------------------------------------------
// K column-sum partials
// ---------------------------------------------------------------------------
__global__ __launch_bounds__(256) void ksum_kernel(const float* __restrict__ Kp,
                                                   float* __restrict__ out)
{
    const int g  = blockIdx.x;
    const int ch = blockIdx.y;
    const int d  = threadIdx.x & 63;
    const int rc = threadIdx.x >> 6;
    const float* Kg = Kp + ((size_t)g * SEQ + ch * 256) * HD;
    float s = 0.f;
    #pragma unroll 8
    for (int r = rc; r < 256; r += 4) s += Kg[r * HD + d];
    __shared__ float red[256];
    red[threadIdx.x] = s;
    __syncthreads();
    if (rc == 0)
        out[(g * 8 + ch) * HD + d] = red[d] + red[64 + d] + red[128 + d] + red[192 + d];
}

// ---------------------------------------------------------------------------
// Single-pass fused attention (R12 dataflow + 32-reg global prefetch):
//   scores: 3xTF32; P: tf32-hi self-normalized; V: tf32-hi.
// CTA = 128 query rows (256 threads, 8 warps x 16 rows).
// ---------------------------------------------------------------------------
#define AT_S  68
#define AT_SV 72
#define SM_K_BYTES (64 * AT_S * 8)
#define SM_V_BYTES (64 * AT_SV * 4)
#define SM_P_BYTES (8 * 16 * AT_S * 4)
#define SM_BYTES (SM_K_BYTES + SM_V_BYTES + SM_P_BYTES)   // 88064 B

__global__ __launch_bounds__(256, 1) void attn_fused(
    const float* __restrict__ Qp, const float* __restrict__ Kp,
    const float* __restrict__ Vp, const float* __restrict__ KsP,
    float* __restrict__ AO)
{
    extern __shared__ float2 sm2[];
    float2* sK2 = sm2;                                // [64][AT_S]
    float*  sVf = (float*)(sK2 + 64 * AT_S);          // [64][AT_SV]
    float*  sP_all = sVf + 64 * AT_SV;                // 8 x [16][AT_S]

    const int tid  = threadIdx.x;
    const int warp = tid >> 5;
    const int lane = tid & 31;
    const int g4   = lane >> 2;
    const int t4   = lane & 3;

    const int mt  = blockIdx.x;
    const int grp = blockIdx.y;
    const float* Qg = Qp + (size_t)grp * SEQ * HD;
    const float* Kg = Kp + (size_t)grp * SEQ * HD;
    const float* Vg = Vp + (size_t)grp * SEQ * HD;
    float*       Og = AO + (size_t)grp * SEQ * HD;

    const int m0 = mt * 128;
    const int wrow = warp * 16;
    float* sPf = sP_all + warp * 16 * AT_S;

    const int row0 = m0 + wrow + g4;
    const int row1 = row0 + 8;
    uint32_t qah[8][4], qal[8][4];
    float mdot0 = 0.f, mdot1 = 0.f;

    #pragma unroll
    for (int kk = 0; kk < 8; kk++) {
        #pragma unroll
        for (int e = 0; e < 2; e++) {
            const int col = kk * 8 + t4 + e * 4;
            float ks = 0.f;
            #pragma unroll
            for (int c = 0; c < 8; c++)
                ks += KsP[(grp * 8 + c) * HD + col];
            float q0 = Qg[(size_t)row0 * HD + col];
            float q1 = Qg[(size_t)row1 * HD + col];
            mdot0 += q0 * ks;
            mdot1 += q1 * ks;
            float h, l;
            split_tf32(q0 * NORMF, h, l);
            qah[kk][e * 2] = __float_as_uint(h);
            qal[kk][e * 2] = __float_as_uint(l);
            split_tf32(q1 * NORMF, h, l);
            qah[kk][e * 2 + 1] = __float_as_uint(h);
            qal[kk][e * 2 + 1] = __float_as_uint(l);
        }
    }
    #pragma unroll
    for (int o = 1; o <= 2; o <<= 1) {
        mdot0 += __shfl_xor_sync(0xffffffffu, mdot0, o);
        mdot1 += __shfl_xor_sync(0xffffffffu, mdot1, o);
    }
    const float mean0 = mdot0 * (NORMF / (float)SEQ);
    const float mean1 = mdot1 * (NORMF / (float)SEQ);

    float oacc[8][4];
    #pragma unroll
    for (int j = 0; j < 8; j++)
        #pragma unroll
        for (int c = 0; c < 4; c++) oacc[j][c] = 0.f;
    float den0 = 0.f, den1 = 0.f;

    // register prefetch buffers: 4 float4 K + 4 float4 V (32 regs)
    float4 kbuf[4], vbuf[4];
    #pragma unroll
    for (int i = 0; i < 4; i++) {
        int j = tid + i * 256;
        int r = j >> 4, c4 = (j & 15) << 2;
        kbuf[i] = *(const float4*)&Kg[(size_t)r * HD + c4];
        vbuf[i] = *(const float4*)&Vg[(size_t)r * HD + c4];
    }

    for (int kt = 0; kt < SEQ / 64; kt++) {
        __syncthreads();
        // split buffered tile into SMEM (K -> hi/lo, V -> hi only)
        #pragma unroll
        for (int i = 0; i < 4; i++) {
            int j = tid + i * 256;
            int r = j >> 4, c4 = (j & 15) << 2;
            float4 s0, s1;
            split_tf32(kbuf[i].x, s0.x, s0.y); split_tf32(kbuf[i].y, s0.z, s0.w);
            split_tf32(kbuf[i].z, s1.x, s1.y); split_tf32(kbuf[i].w, s1.z, s1.w);
            *(float4*)&sK2[r * AT_S + c4]     = s0;
            *(float4*)&sK2[r * AT_S + c4 + 2] = s1;
            float4 vh;
            vh.x = __uint_as_float(to_tf32(vbuf[i].x));
            vh.y = __uint_as_float(to_tf32(vbuf[i].y));
            vh.z = __uint_as_float(to_tf32(vbuf[i].z));
            vh.w = __uint_as_float(to_tf32(vbuf[i].w));
            *(float4*)&sVf[r * AT_SV + c4] = vh;
        }
        __syncthreads();

        // prefetch next tile while mma runs
        if (kt + 1 < SEQ / 64) {
            const size_t base = (size_t)(kt + 1) * 64;
            #pragma unroll
            for (int i = 0; i < 4; i++) {
                int j = tid + i * 256;
                int r = j >> 4, c4 = (j & 15) << 2;
                kbuf[i] = *(const float4*)&Kg[(base + r) * HD + c4];
                vbuf[i] = *(const float4*)&Vg[(base + r) * HD + c4];
            }
        }

        // S = Qs @ K^T (3xTF32)
        float sacc[8][4];
        #pragma unroll
        for (int j = 0; j < 8; j++)
            #pragma unroll
            for (int c = 0; c < 4; c++) sacc[j][c] = 0.f;

        #pragma unroll
        for (int kk = 0; kk < 8; kk++) {
            const int k0 = kk * 8;
            #pragma unroll
            for (int j = 0; j < 8; j++) {
                const int brow = j * 8 + g4;
                float2 b0 = sK2[brow * AT_S + k0 + t4];
                float2 b1 = sK2[brow * AT_S + k0 + t4 + 4];
                uint32_t bh[2] = {__float_as_uint(b0.x), __float_as_uint(b1.x)};
                uint32_t bl[2] = {__float_as_uint(b0.y), __float_as_uint(b1.y)};
                mma3(sacc[j], qah[kk], qal[kk], bh, bl);
            }
        }

        // mask + exp -> quantize P to tf32-hi; denom from the SAME hi values
        #pragma unroll
        for (int j = 0; j < 8; j++) {
            float p0 = (sacc[j][0] > mean0) ? __expf(sacc[j][0]) : 0.f;
            float p1 = (sacc[j][1] > mean0) ? __expf(sacc[j][1]) : 0.f;
            float p2 = (sacc[j][2] > mean1) ? __expf(sacc[j][2]) : 0.f;
            float p3 = (sacc[j][3] > mean1) ? __expf(sacc[j][3]) : 0.f;
            float h0 = __uint_as_float(to_tf32(p0));
            float h1 = __uint_as_float(to_tf32(p1));
            float h2 = __uint_as_float(to_tf32(p2));
            float h3 = __uint_as_float(to_tf32(p3));
            den0 += h0 + h1;
            den1 += h2 + h3;
            *(float2*)&sPf[g4       * AT_S + j * 8 + 2 * t4] = make_float2(h0, h1);
            *(float2*)&sPf[(g4 + 8) * AT_S + j * 8 + 2 * t4] = make_float2(h2, h3);
        }
        __syncwarp();

        // O += P_hi @ V_hi  (1 mma per step)
        #pragma unroll
        for (int kk = 0; kk < 8; kk++) {
            const int k0 = kk * 8;
            uint32_t ah[4];
            ah[0] = __float_as_uint(sPf[g4       * AT_S + k0 + t4]);
            ah[1] = __float_as_uint(sPf[(g4 + 8) * AT_S + k0 + t4]);
            ah[2] = __float_as_uint(sPf[g4       * AT_S + k0 + t4 + 4]);
            ah[3] = __float_as_uint(sPf[(g4 + 8) * AT_S + k0 + t4 + 4]);
            #pragma unroll
            for (int j = 0; j < 8; j++) {
                const int bcol = j * 8 + g4;
                uint32_t bh[2];
                bh[0] = __float_as_uint(sVf[(k0 + t4)     * AT_SV + bcol]);
                bh[1] = __float_as_uint(sVf[(k0 + t4 + 4) * AT_SV + bcol]);
                mma_tf32(oacc[j], ah, bh);
            }
        }
    }

    #pragma unroll
    for (int o = 1; o <= 2; o <<= 1) {
        den0 += __shfl_xor_sync(0xffffffffu, den0, o);
        den1 += __shfl_xor_sync(0xffffffffu, den1, o);
    }
    const float inv0 = 1.f / den0;
    const float inv1 = 1.f / den1;

    #pragma unroll
    for (int j = 0; j < 8; j++) {
        const int col = j * 8 + 2 * t4;
        *(float2*)&Og[(size_t)row0 * HD + col] =
            make_float2(oacc[j][0] * inv0, oacc[j][1] * inv0);
        *(float2*)&Og[(size_t)row1 * HD + col] =
            make_float2(oacc[j][2] * inv1, oacc[j][3] * inv1);
    }
}

// ---------------------------------------------------------------------------
// Launch
// ---------------------------------------------------------------------------
extern "C" void kernel_launch(void* const* d_in, const int* in_sizes, int n_in,
                              void* d_out, int out_size)
{
    const float* x   = (const float*)d_in[0];
    const float* y   = (const float*)d_in[1];
    const float* q_w = (const float*)d_in[2];
    const float* q_b = (const float*)d_in[3];
    const float* k_w = (const float*)d_in[4];
    const float* k_b = (const float*)d_in[5];
    const float* v_w = (const float*)d_in[6];
    const float* v_b = (const float*)d_in[7];
    const float* o_w = (const float*)d_in[8];
    const float* o_b = (const float*)d_in[9];
    float* out = (float*)d_out;

    float *Qp, *Kp, *Vp, *AO, *KsP;
    cudaGetSymbolAddress((void**)&Qp, g_Qp);
    cudaGetSymbolAddress((void**)&Kp, g_Kp);
    cudaGetSymbolAddress((void**)&Vp, g_Vp);
    cudaGetSymbolAddress((void**)&AO, g_AO);
    cudaGetSymbolAddress((void**)&KsP, g_KsumP);

    static int smem_set = 0;
    if (!smem_set) {
        cudaFuncSetAttribute(attn_fused,
                             cudaFuncAttributeMaxDynamicSharedMemorySize, SM_BYTES);
        smem_set = 1;
    }

    // Fused Q/K/V projections (3xBF16 tensor core) — one launch, 384 CTAs
    gemm_qkv<<<dim3(4, 32, 3), 256>>>(
        x, y, q_w, q_b, k_w, k_b, v_w, v_b, Qp, Kp, Vp);

    // K column-sum partials (for mean thresholds)
    ksum_kernel<<<dim3(NG, 8), 256>>>(Kp, KsP);

    // Fused single-pass attention (128 Q rows per CTA, register prefetch)
    attn_fused<<<dim3(SEQ / 128, NG), 256, SM_BYTES>>>(Qp, Kp, Vp, KsP, AO);

    // Output projection (3xBF16 tensor core)
    gemm_oproj<<<dim3(4, 32), 256>>>(AO, o_w, o_b, out);
}

// round 15
// speedup vs baseline: 2.0524x; 1.0757x over previous
#include <cuda_runtime.h>
#include <cuda_bf16.h>
#include <math.h>
#include <stdint.h>

// Problem constants
#define DM   512
#define SEQ  2048
#define BB   2
#define NH   8
#define HD   64
#define MTOK (BB*SEQ)     // 4096 tokens
#define NG   (NH*BB)      // 16 attention groups

#define NORMF 0.04419417382415922f  // 1/sqrt(512)

// Scratch (static device globals; allocation is forbidden)
__device__ float g_Qp[MTOK * DM];
__device__ float g_Kp[MTOK * DM];
__device__ float g_Vp[MTOK * DM];
__device__ float g_AO[MTOK * DM];
__device__ float g_KsumP[NG * 8 * HD];

// ---------------------------------------------------------------------------
// mma wrappers + split helpers
// ---------------------------------------------------------------------------
__device__ __forceinline__ void mma_tf32(float* c, const uint32_t* a, const uint32_t* b)
{
    asm volatile(
        "mma.sync.aligned.m16n8k8.row.col.f32.tf32.tf32.f32 "
        "{%0,%1,%2,%3}, {%4,%5,%6,%7}, {%8,%9}, {%0,%1,%2,%3};\n"
        : "+f"(c[0]), "+f"(c[1]), "+f"(c[2]), "+f"(c[3])
        : "r"(a[0]), "r"(a[1]), "r"(a[2]), "r"(a[3]), "r"(b[0]), "r"(b[1]));
}

__device__ __forceinline__ void mma_bf16(float* c, const uint32_t* a, const uint32_t* b)
{
    asm volatile(
        "mma.sync.aligned.m16n8k16.row.col.f32.bf16.bf16.f32 "
        "{%0,%1,%2,%3}, {%4,%5,%6,%7}, {%8,%9}, {%0,%1,%2,%3};\n"
        : "+f"(c[0]), "+f"(c[1]), "+f"(c[2]), "+f"(c[3])
        : "r"(a[0]), "r"(a[1]), "r"(a[2]), "r"(a[3]), "r"(b[0]), "r"(b[1]));
}

__device__ __forceinline__ uint32_t to_tf32(float x)
{
    uint32_t r;
    asm("cvt.rna.tf32.f32 %0, %1;\n" : "=r"(r) : "f"(x));
    return r;
}

__device__ __forceinline__ void split_tf32(float x, float& hi, float& lo)
{
    hi = __uint_as_float(to_tf32(x));
    lo = x - hi;
}

__device__ __forceinline__ void mma3(float* c,
                                     const uint32_t* ah, const uint32_t* al,
                                     const uint32_t* bh, const uint32_t* bl)
{
    mma_tf32(c, ah, bl);
    mma_tf32(c, al, bh);
    mma_tf32(c, ah, bh);
}

__device__ __forceinline__ void mma3_bf16(float* c,
                                          const uint32_t* ah, const uint32_t* al,
                                          const uint32_t* bh, const uint32_t* bl)
{
    mma_bf16(c, ah, bl);
    mma_bf16(c, al, bh);
    mma_bf16(c, ah, bh);
}

// pack 2 floats into bf16x2 (lower half = f0)
__device__ __forceinline__ uint32_t bf16x2(float f0, float f1)
{
    uint32_t r;
    asm("cvt.rn.bf16x2.f32 %0, %1, %2;\n" : "=r"(r) : "f"(f1), "f"(f0));
    return r;
}

// split pair (f0,f1) into bf16x2 hi + bf16x2 lo planes
__device__ __forceinline__ void split_bf16x2(float f0, float f1,
                                             uint32_t& hp, uint32_t& lp)
{
    hp = bf16x2(f0, f1);
    float h0 = __uint_as_float(hp << 16);
    float h1 = __uint_as_float(hp & 0xFFFF0000u);
    lp = bf16x2(f0 - h0, f1 - h1);
}

// ---------------------------------------------------------------------------
// 3xBF16 NT projection GEMM: C[4096,512] = A @ W^T + bias  (UNCHANGED R14)
// ---------------------------------------------------------------------------
#define BQ_S 20

__device__ __forceinline__ void gemm_bf16_body(
    const float* __restrict__ A, const float* __restrict__ W,
    const float* __restrict__ bias, float* __restrict__ C)
{
    __shared__ uint32_t sAh[128 * BQ_S], sAl[128 * BQ_S];
    __shared__ uint32_t sWh[128 * BQ_S], sWl[128 * BQ_S];

    const int tid  = threadIdx.x;
    const int warp = tid >> 5;
    const int lane = tid & 31;
    const int g4   = lane >> 2;
    const int t4   = lane & 3;
    const int wm   = warp >> 2;   // 0..1
    const int wn   = warp & 3;    // 0..3
    const int m0   = blockIdx.y * 128;
    const int n0   = blockIdx.x * 128;

    float acc[4][4][4];
    #pragma unroll
    for (int mf = 0; mf < 4; mf++)
        #pragma unroll
        for (int nf = 0; nf < 4; nf++)
            #pragma unroll
            for (int c = 0; c < 4; c++) acc[mf][nf][c] = 0.f;

    int lr[4], lk[4];
    #pragma unroll
    for (int i = 0; i < 4; i++) {
        int pos = tid + i * 256;
        lr[i] = pos >> 3;
        lk[i] = (pos & 7) << 2;
    }

    float4 ab[4], wb[4];
    #pragma unroll
    for (int i = 0; i < 4; i++) {
        ab[i] = *(const float4*)&A[(size_t)(m0 + lr[i]) * DM + lk[i]];
        wb[i] = *(const float4*)&W[(size_t)(n0 + lr[i]) * DM + lk[i]];
    }

    for (int kt = 0; kt < DM / 32; kt++) {
        __syncthreads();
        #pragma unroll
        for (int i = 0; i < 4; i++) {
            uint32_t h0, l0, h1, l1;
            const int idx = lr[i] * BQ_S + (lk[i] >> 1);
            split_bf16x2(ab[i].x, ab[i].y, h0, l0);
            split_bf16x2(ab[i].z, ab[i].w, h1, l1);
            sAh[idx] = h0; sAh[idx + 1] = h1;
            sAl[idx] = l0; sAl[idx + 1] = l1;
            split_bf16x2(wb[i].x, wb[i].y, h0, l0);
            split_bf16x2(wb[i].z, wb[i].w, h1, l1);
            sWh[idx] = h0; sWh[idx + 1] = h1;
            sWl[idx] = l0; sWl[idx + 1] = l1;
        }
        __syncthreads();

        if (kt + 1 < DM / 32) {
            const int k0n = (kt + 1) * 32;
            #pragma unroll
            for (int i = 0; i < 4; i++) {
                ab[i] = *(const float4*)&A[(size_t)(m0 + lr[i]) * DM + k0n + lk[i]];
                wb[i] = *(const float4*)&W[(size_t)(n0 + lr[i]) * DM + k0n + lk[i]];
            }
        }

        #pragma unroll
        for (int ks = 0; ks < 2; ks++) {
            const int cb = ks * 8 + t4;
            uint32_t ah[4][4], al[4][4];
            #pragma unroll
            for (int mf = 0; mf < 4; mf++) {
                const int rb = wm * 64 + mf * 16;
                ah[mf][0] = sAh[(rb + g4)     * BQ_S + cb];
                ah[mf][1] = sAh[(rb + g4 + 8) * BQ_S + cb];
                ah[mf][2] = sAh[(rb + g4)     * BQ_S + cb + 4];
                ah[mf][3] = sAh[(rb + g4 + 8) * BQ_S + cb + 4];
                al[mf][0] = sAl[(rb + g4)     * BQ_S + cb];
                al[mf][1] = sAl[(rb + g4 + 8) * BQ_S + cb];
                al[mf][2] = sAl[(rb + g4)     * BQ_S + cb + 4];
                al[mf][3] = sAl[(rb + g4 + 8) * BQ_S + cb + 4];
            }
            #pragma unroll
            for (int nf = 0; nf < 4; nf++) {
                const int nr = wn * 32 + nf * 8 + g4;
                uint32_t bh[2], bl[2];
                bh[0] = sWh[nr * BQ_S + cb];
                bh[1] = sWh[nr * BQ_S + cb + 4];
                bl[0] = sWl[nr * BQ_S + cb];
                bl[1] = sWl[nr * BQ_S + cb + 4];
                #pragma unroll
                for (int mf = 0; mf < 4; mf++)
                    mma3_bf16(acc[mf][nf], ah[mf], al[mf], bh, bl);
            }
        }
    }

    #pragma unroll
    for (int nf = 0; nf < 4; nf++) {
        const int col = n0 + wn * 32 + nf * 8 + 2 * t4;
        const float b0 = bias[col], b1 = bias[col + 1];
        #pragma unroll
        for (int mf = 0; mf < 4; mf++) {
            const int r0 = m0 + wm * 64 + mf * 16 + g4;
            *(float2*)&C[(size_t)r0 * DM + col] =
                make_float2(acc[mf][nf][0] + b0, acc[mf][nf][1] + b1);
            *(float2*)&C[(size_t)(r0 + 8) * DM + col] =
                make_float2(acc[mf][nf][2] + b0, acc[mf][nf][3] + b1);
        }
    }
}

__global__ __launch_bounds__(256) void gemm_qkv(
    const float* __restrict__ x, const float* __restrict__ y,
    const float* __restrict__ q_w, const float* __restrict__ q_b,
    const float* __restrict__ k_w, const float* __restrict__ k_b,
    const float* __restrict__ v_w, const float* __restrict__ v_b,
    float* __restrict__ Qp, float* __restrict__ Kp, float* __restrict__ Vp)
{
    const float *A, *W, *bias;
    float* C;
    if (blockIdx.z == 0)      { A = x; W = q_w; bias = q_b; C = Qp; }
    else if (blockIdx.z == 1) { A = y; W = k_w; bias = k_b; C = Kp; }
    else                      { A = y; W = v_w; bias = v_b; C = Vp; }
    gemm_bf16_body(A, W, bias, C);
}

__global__ __launch_bounds__(256) void gemm_oproj(
    const float* __restrict__ A, const float* __restrict__ W,
    const float* __restrict__ bias, float* __restrict__ C)
{
    gemm_bf16_body(A, W, bias, C);
}

// ---------------------------------------------------------------------------
// K column-sum partials
// ---------------------------------------------------------------------------
__global__ __launch_bounds__(256) void ksum_kernel(const float* __restrict__ Kp,
                                                   float* __restrict__ out)
{
    const int g  = blockIdx.x;
    const int ch = blockIdx.y;
    const int d  = threadIdx.x & 63;
    const int rc = threadIdx.x >> 6;
    const float* Kg = Kp + ((size_t)g * SEQ + ch * 256) * HD;
    float s = 0.f;
    #pragma unroll 8
    for (int r = rc; r < 256; r += 4) s += Kg[r * HD + d];
    __shared__ float red[256];
    red[threadIdx.x] = s;
    __syncthreads();
    if (rc == 0)
        out[(g * 8 + ch) * HD + d] = red[d] + red[64 + d] + red[128 + d] + red[192 + d];
}

// ---------------------------------------------------------------------------
// Single-pass fused attention, double-buffered K/V SMEM (1 sync per tile):
//   scores: 3xTF32; P: tf32-hi self-normalized; V: tf32-hi.
// CTA = 128 query rows (256 threads, 8 warps x 16 rows).
// ---------------------------------------------------------------------------
#define AT_S  68
#define AT_SV 72
#define KBUF_F2 (64 * AT_S)                      // float2 elems per K buffer
#define VBUF_F  (64 * AT_SV)                     // floats per V buffer
#define SM_BYTES (2 * KBUF_F2 * 8 + 2 * VBUF_F * 4 + 8 * 16 * AT_S * 4)  // 141312

__global__ __launch_bounds__(256, 1) void attn_fused(
    const float* __restrict__ Qp, const float* __restrict__ Kp,
    const float* __restrict__ Vp, const float* __restrict__ KsP,
    float* __restrict__ AO)
{
    extern __shared__ float2 sm2[];
    float2* sKb = sm2;                                  // 2 x [64][AT_S]
    float*  sVb = (float*)(sKb + 2 * KBUF_F2);          // 2 x [64][AT_SV]
    float*  sP_all = sVb + 2 * VBUF_F;                  // 8 x [16][AT_S]

    const int tid  = threadIdx.x;
    const int warp = tid >> 5;
    const int lane = tid & 31;
    const int g4   = lane >> 2;
    const int t4   = lane & 3;

    const int mt  = blockIdx.x;
    const int grp = blockIdx.y;
    const float* Qg = Qp + (size_t)grp * SEQ * HD;
    const float* Kg = Kp + (size_t)grp * SEQ * HD;
    const float* Vg = Vp + (size_t)grp * SEQ * HD;
    float*       Og = AO + (size_t)grp * SEQ * HD;

    const int m0 = mt * 128;
    const int wrow = warp * 16;
    float* sPf = sP_all + warp * 16 * AT_S;

    // per-thread tile coords
    int trr[4], tcc[4];
    #pragma unroll
    for (int i = 0; i < 4; i++) {
        int j = tid + i * 256;
        trr[i] = j >> 4;
        tcc[i] = (j & 15) << 2;
    }

    // --- Q fragments (registers) + row means via K column-sums ---
    const int row0 = m0 + wrow + g4;
    const int row1 = row0 + 8;
    uint32_t qah[8][4], qal[8][4];
    float mdot0 = 0.f, mdot1 = 0.f;

    #pragma unroll
    for (int kk = 0; kk < 8; kk++) {
        #pragma unroll
        for (int e = 0; e < 2; e++) {
            const int col = kk * 8 + t4 + e * 4;
            float ks = 0.f;
            #pragma unroll
            for (int c = 0; c < 8; c++)
                ks += KsP[(grp * 8 + c) * HD + col];
            float q0 = Qg[(size_t)row0 * HD + col];
            float q1 = Qg[(size_t)row1 * HD + col];
            mdot0 += q0 * ks;
            mdot1 += q1 * ks;
            float h, l;
            split_tf32(q0 * NORMF, h, l);
            qah[kk][e * 2] = __float_as_uint(h);
            qal[kk][e * 2] = __float_as_uint(l);
            split_tf32(q1 * NORMF, h, l);
            qah[kk][e * 2 + 1] = __float_as_uint(h);
            qal[kk][e * 2 + 1] = __float_as_uint(l);
        }
    }
    #pragma unroll
    for (int o = 1; o <= 2; o <<= 1) {
        mdot0 += __shfl_xor_sync(0xffffffffu, mdot0, o);
        mdot1 += __shfl_xor_sync(0xffffffffu, mdot1, o);
    }
    const float mean0 = mdot0 * (NORMF / (float)SEQ);
    const float mean1 = mdot1 * (NORMF / (float)SEQ);

    float oacc[8][4];
    #pragma unroll
    for (int j = 0; j < 8; j++)
        #pragma unroll
        for (int c = 0; c < 4; c++) oacc[j][c] = 0.f;
    float den0 = 0.f, den1 = 0.f;

    // prologue: load tile 0, store into buffer 0
    float4 kbuf[4], vbuf[4];
    #pragma unroll
    for (int i = 0; i < 4; i++) {
        kbuf[i] = *(const float4*)&Kg[(size_t)trr[i] * HD + tcc[i]];
        vbuf[i] = *(const float4*)&Vg[(size_t)trr[i] * HD + tcc[i]];
    }
    {
        float2* sK2 = sKb;
        float*  sVf = sVb;
        #pragma unroll
        for (int i = 0; i < 4; i++) {
            float4 s0, s1;
            split_tf32(kbuf[i].x, s0.x, s0.y); split_tf32(kbuf[i].y, s0.z, s0.w);
            split_tf32(kbuf[i].z, s1.x, s1.y); split_tf32(kbuf[i].w, s1.z, s1.w);
            *(float4*)&sK2[trr[i] * AT_S + tcc[i]]     = s0;
            *(float4*)&sK2[trr[i] * AT_S + tcc[i] + 2] = s1;
            float4 vh;
            vh.x = __uint_as_float(to_tf32(vbuf[i].x));
            vh.y = __uint_as_float(to_tf32(vbuf[i].y));
            vh.z = __uint_as_float(to_tf32(vbuf[i].z));
            vh.w = __uint_as_float(to_tf32(vbuf[i].w));
            *(float4*)&sVf[trr[i] * AT_SV + tcc[i]] = vh;
        }
    }
    __syncthreads();

    for (int kt = 0; kt < SEQ / 64; kt++) {
        const int cur = kt & 1;
        float2* sK2 = sKb + cur * KBUF_F2;
        float*  sVf = sVb + cur * VBUF_F;

        // prefetch next tile into registers (overlaps the mma below)
        const bool more = (kt + 1 < SEQ / 64);
        if (more) {
            const size_t base = (size_t)(kt + 1) * 64;
            #pragma unroll
            for (int i = 0; i < 4; i++) {
                kbuf[i] = *(const float4*)&Kg[(base + trr[i]) * HD + tcc[i]];
                vbuf[i] = *(const float4*)&Vg[(base + trr[i]) * HD + tcc[i]];
            }
        }

        // S = Qs @ K^T (3xTF32)
        float sacc[8][4];
        #pragma unroll
        for (int j = 0; j < 8; j++)
            #pragma unroll
            for (int c = 0; c < 4; c++) sacc[j][c] = 0.f;

        #pragma unroll
        for (int kk = 0; kk < 8; kk++) {
            const int k0 = kk * 8;
            #pragma unroll
            for (int j = 0; j < 8; j++) {
                const int brow = j * 8 + g4;
                float2 b0 = sK2[brow * AT_S + k0 + t4];
                float2 b1 = sK2[brow * AT_S + k0 + t4 + 4];
                uint32_t bh[2] = {__float_as_uint(b0.x), __float_as_uint(b1.x)};
                uint32_t bl[2] = {__float_as_uint(b0.y), __float_as_uint(b1.y)};
                mma3(sacc[j], qah[kk], qal[kk], bh, bl);
            }
        }

        // mask + exp -> quantize P to tf32-hi; denom from the SAME hi values
        #pragma unroll
        for (int j = 0; j < 8; j++) {
            float p0 = (sacc[j][0] > mean0) ? __expf(sacc[j][0]) : 0.f;
            float p1 = (sacc[j][1] > mean0) ? __expf(sacc[j][1]) : 0.f;
            float p2 = (sacc[j][2] > mean1) ? __expf(sacc[j][2]) : 0.f;
            float p3 = (sacc[j][3] > mean1) ? __expf(sacc[j][3]) : 0.f;
            float h0 = __uint_as_float(to_tf32(p0));
            float h1 = __uint_as_float(to_tf32(p1));
            float h2 = __uint_as_float(to_tf32(p2));
            float h3 = __uint_as_float(to_tf32(p3));
            den0 += h0 + h1;
            den1 += h2 + h3;
            *(float2*)&sPf[g4       * AT_S + j * 8 + 2 * t4] = make_float2(h0, h1);
            *(float2*)&sPf[(g4 + 8) * AT_S + j * 8 + 2 * t4] = make_float2(h2, h3);
        }
        __syncwarp();

        // O += P_hi @ V_hi
        #pragma unroll
        for (int kk = 0; kk < 8; kk++) {
            const int k0 = kk * 8;
            uint32_t ah[4];
            ah[0] = __float_as_uint(sPf[g4       * AT_S + k0 + t4]);
            ah[1] = __float_as_uint(sPf[(g4 + 8) * AT_S + k0 + t4]);
            ah[2] = __float_as_uint(sPf[g4       * AT_S + k0 + t4 + 4]);
            ah[3] = __float_as_uint(sPf[(g4 + 8) * AT_S + k0 + t4 + 4]);
            #pragma unroll
            for (int j = 0; j < 8; j++) {
                const int bcol = j * 8 + g4;
                uint32_t bh[2];
                bh[0] = __float_as_uint(sVf[(k0 + t4)     * AT_SV + bcol]);
                bh[1] = __float_as_uint(sVf[(k0 + t4 + 4) * AT_SV + bcol]);
                mma_tf32(oacc[j], ah, bh);
            }
        }

        // store prefetched tile into the OTHER buffer (no conflict with
        // laggard warps still doing mma on buf[cur]); then single sync.
        if (more) {
            float2* nK2 = sKb + (1 - cur) * KBUF_F2;
            float*  nVf = sVb + (1 - cur) * VBUF_F;
            #pragma unroll
            for (int i = 0; i < 4; i++) {
                float4 s0, s1;
                split_tf32(kbuf[i].x, s0.x, s0.y); split_tf32(kbuf[i].y, s0.z, s0.w);
                split_tf32(kbuf[i].z, s1.x, s1.y); split_tf32(kbuf[i].w, s1.z, s1.w);
                *(float4*)&nK2[trr[i] * AT_S + tcc[i]]     = s0;
                *(float4*)&nK2[trr[i] * AT_S + tcc[i] + 2] = s1;
                float4 vh;
                vh.x = __uint_as_float(to_tf32(vbuf[i].x));
                vh.y = __uint_as_float(to_tf32(vbuf[i].y));
                vh.z = __uint_as_float(to_tf32(vbuf[i].z));
                vh.w = __uint_as_float(to_tf32(vbuf[i].w));
                *(float4*)&nVf[trr[i] * AT_SV + tcc[i]] = vh;
            }
            __syncthreads();
        }
    }

    // reduce denominators, normalize, write out
    #pragma unroll
    for (int o = 1; o <= 2; o <<= 1) {
        den0 += __shfl_xor_sync(0xffffffffu, den0, o);
        den1 += __shfl_xor_sync(0xffffffffu, den1, o);
    }
    const float inv0 = 1.f / den0;
    const float inv1 = 1.f / den1;

    #pragma unroll
    for (int j = 0; j < 8; j++) {
        const int col = j * 8 + 2 * t4;
        *(float2*)&Og[(size_t)row0 * HD + col] =
            make_float2(oacc[j][0] * inv0, oacc[j][1] * inv0);
        *(float2*)&Og[(size_t)row1 * HD + col] =
            make_float2(oacc[j][2] * inv1, oacc[j][3] * inv1);
    }
}

// ---------------------------------------------------------------------------
// Launch
// ---------------------------------------------------------------------------
extern "C" void kernel_launch(void* const* d_in, const int* in_sizes, int n_in,
                              void* d_out, int out_size)
{
    const float* x   = (const float*)d_in[0];
    const float* y   = (const float*)d_in[1];
    const float* q_w = (const float*)d_in[2];
    const float* q_b = (const float*)d_in[3];
    const float* k_w = (const float*)d_in[4];
    const float* k_b = (const float*)d_in[5];
    const float* v_w = (const float*)d_in[6];
    const float* v_b = (const float*)d_in[7];
    const float* o_w = (const float*)d_in[8];
    const float* o_b = (const float*)d_in[9];
    float* out = (float*)d_out;

    float *Qp, *Kp, *Vp, *AO, *KsP;
    cudaGetSymbolAddress((void**)&Qp, g_Qp);
    cudaGetSymbolAddress((void**)&Kp, g_Kp);
    cudaGetSymbolAddress((void**)&Vp, g_Vp);
    cudaGetSymbolAddress((void**)&AO, g_AO);
    cudaGetSymbolAddress((void**)&KsP, g_KsumP);

    static int smem_set = 0;
    if (!smem_set) {
        cudaFuncSetAttribute(attn_fused,
                             cudaFuncAttributeMaxDynamicSharedMemorySize, SM_BYTES);
        smem_set = 1;
    }

    // Fused Q/K/V projections (3xBF16 tensor core) — one launch, 384 CTAs
    gemm_qkv<<<dim3(4, 32, 3), 256>>>(
        x, y, q_w, q_b, k_w, k_b, v_w, v_b, Qp, Kp, Vp);

    // K column-sum partials (for mean thresholds)
    ksum_kernel<<<dim3(NG, 8), 256>>>(Kp, KsP);

    // Fused single-pass attention (128 Q rows per CTA, double-buffered K/V)
    attn_fused<<<dim3(SEQ / 128, NG), 256, SM_BYTES>>>(Qp, Kp, Vp, KsP, AO);

    // Output projection (3xBF16 tensor core)
    gemm_oproj<<<dim3(4, 32), 256>>>(AO, o_w, o_b, out);
}

// round 17
// speedup vs baseline: 2.5513x; 1.2431x over previous
#include <cuda_runtime.h>
#include <cuda_bf16.h>
#include <math.h>
#include <stdint.h>

// Problem constants
#define DM   512
#define SEQ  2048
#define BB   2
#define NH   8
#define HD   64
#define MTOK (BB*SEQ)     // 4096 tokens
#define NG   (NH*BB)      // 16 attention groups

#define NORMF 0.04419417382415922f  // 1/sqrt(512)

// Scratch (static device globals; allocation is forbidden)
__device__ float g_Qp[MTOK * DM];
__device__ float g_Kp[MTOK * DM];
__device__ float g_Vp[MTOK * DM];
__device__ float g_AO[MTOK * DM];
__device__ float g_KsumP[NG * 8 * HD];

// ---------------------------------------------------------------------------
// mma wrappers + split helpers
// ---------------------------------------------------------------------------
__device__ __forceinline__ void mma_tf32(float* c, const uint32_t* a, const uint32_t* b)
{
    asm volatile(
        "mma.sync.aligned.m16n8k8.row.col.f32.tf32.tf32.f32 "
        "{%0,%1,%2,%3}, {%4,%5,%6,%7}, {%8,%9}, {%0,%1,%2,%3};\n"
        : "+f"(c[0]), "+f"(c[1]), "+f"(c[2]), "+f"(c[3])
        : "r"(a[0]), "r"(a[1]), "r"(a[2]), "r"(a[3]), "r"(b[0]), "r"(b[1]));
}

__device__ __forceinline__ void mma_bf16(float* c, const uint32_t* a, const uint32_t* b)
{
    asm volatile(
        "mma.sync.aligned.m16n8k16.row.col.f32.bf16.bf16.f32 "
        "{%0,%1,%2,%3}, {%4,%5,%6,%7}, {%8,%9}, {%0,%1,%2,%3};\n"
        : "+f"(c[0]), "+f"(c[1]), "+f"(c[2]), "+f"(c[3])
        : "r"(a[0]), "r"(a[1]), "r"(a[2]), "r"(a[3]), "r"(b[0]), "r"(b[1]));
}

__device__ __forceinline__ uint32_t to_tf32(float x)
{
    uint32_t r;
    asm("cvt.rna.tf32.f32 %0, %1;\n" : "=r"(r) : "f"(x));
    return r;
}

__device__ __forceinline__ void split_tf32(float x, float& hi, float& lo)
{
    hi = __uint_as_float(to_tf32(x));
    lo = x - hi;
}

__device__ __forceinline__ void mma3_bf16(float* c,
                                          const uint32_t* ah, const uint32_t* al,
                                          const uint32_t* bh, const uint32_t* bl)
{
    mma_bf16(c, ah, bl);
    mma_bf16(c, al, bh);
    mma_bf16(c, ah, bh);
}

// pack 2 floats into bf16x2 (lower half = f0)
__device__ __forceinline__ uint32_t bf16x2(float f0, float f1)
{
    uint32_t r;
    asm("cvt.rn.bf16x2.f32 %0, %1, %2;\n" : "=r"(r) : "f"(f1), "f"(f0));
    return r;
}

// split pair (f0,f1) into bf16x2 hi + bf16x2 lo planes
__device__ __forceinline__ void split_bf16x2(float f0, float f1,
                                             uint32_t& hp, uint32_t& lp)
{
    hp = bf16x2(f0, f1);
    float h0 = __uint_as_float(hp << 16);
    float h1 = __uint_as_float(hp & 0xFFFF0000u);
    lp = bf16x2(f0 - h0, f1 - h1);
}

// ---------------------------------------------------------------------------
// 3xBF16 NT projection GEMM: C[4096,512] = A @ W^T + bias  (UNCHANGED)
// ---------------------------------------------------------------------------
#define BQ_S 20

__device__ __forceinline__ void gemm_bf16_body(
    const float* __restrict__ A, const float* __restrict__ W,
    const float* __restrict__ bias, float* __restrict__ C)
{
    __shared__ uint32_t sAh[128 * BQ_S], sAl[128 * BQ_S];
    __shared__ uint32_t sWh[128 * BQ_S], sWl[128 * BQ_S];

    const int tid  = threadIdx.x;
    const int warp = tid >> 5;
    const int lane = tid & 31;
    const int g4   = lane >> 2;
    const int t4   = lane & 3;
    const int wm   = warp >> 2;
    const int wn   = warp & 3;
    const int m0   = blockIdx.y * 128;
    const int n0   = blockIdx.x * 128;

    float acc[4][4][4];
    #pragma unroll
    for (int mf = 0; mf < 4; mf++)
        #pragma unroll
        for (int nf = 0; nf < 4; nf++)
            #pragma unroll
            for (int c = 0; c < 4; c++) acc[mf][nf][c] = 0.f;

    int lr[4], lk[4];
    #pragma unroll
    for (int i = 0; i < 4; i++) {
        int pos = tid + i * 256;
        lr[i] = pos >> 3;
        lk[i] = (pos & 7) << 2;
    }

    float4 ab[4], wb[4];
    #pragma unroll
    for (int i = 0; i < 4; i++) {
        ab[i] = *(const float4*)&A[(size_t)(m0 + lr[i]) * DM + lk[i]];
        wb[i] = *(const float4*)&W[(size_t)(n0 + lr[i]) * DM + lk[i]];
    }

    for (int kt = 0; kt < DM / 32; kt++) {
        __syncthreads();
        #pragma unroll
        for (int i = 0; i < 4; i++) {
            uint32_t h0, l0, h1, l1;
            const int idx = lr[i] * BQ_S + (lk[i] >> 1);
            split_bf16x2(ab[i].x, ab[i].y, h0, l0);
            split_bf16x2(ab[i].z, ab[i].w, h1, l1);
            sAh[idx] = h0; sAh[idx + 1] = h1;
            sAl[idx] = l0; sAl[idx + 1] = l1;
            split_bf16x2(wb[i].x, wb[i].y, h0, l0);
            split_bf16x2(wb[i].z, wb[i].w, h1, l1);
            sWh[idx] = h0; sWh[idx + 1] = h1;
            sWl[idx] = l0; sWl[idx + 1] = l1;
        }
        __syncthreads();

        if (kt + 1 < DM / 32) {
            const int k0n = (kt + 1) * 32;
            #pragma unroll
            for (int i = 0; i < 4; i++) {
                ab[i] = *(const float4*)&A[(size_t)(m0 + lr[i]) * DM + k0n + lk[i]];
                wb[i] = *(const float4*)&W[(size_t)(n0 + lr[i]) * DM + k0n + lk[i]];
            }
        }

        #pragma unroll
        for (int ks = 0; ks < 2; ks++) {
            const int cb = ks * 8 + t4;
            uint32_t ah[4][4], al[4][4];
            #pragma unroll
            for (int mf = 0; mf < 4; mf++) {
                const int rb = wm * 64 + mf * 16;
                ah[mf][0] = sAh[(rb + g4)     * BQ_S + cb];
                ah[mf][1] = sAh[(rb + g4 + 8) * BQ_S + cb];
                ah[mf][2] = sAh[(rb + g4)     * BQ_S + cb + 4];
                ah[mf][3] = sAh[(rb + g4 + 8) * BQ_S + cb + 4];
                al[mf][0] = sAl[(rb + g4)     * BQ_S + cb];
                al[mf][1] = sAl[(rb + g4 + 8) * BQ_S + cb];
                al[mf][2] = sAl[(rb + g4)     * BQ_S + cb + 4];
                al[mf][3] = sAl[(rb + g4 + 8) * BQ_S + cb + 4];
            }
            #pragma unroll
            for (int nf = 0; nf < 4; nf++) {
                const int nr = wn * 32 + nf * 8 + g4;
                uint32_t bh[2], bl[2];
                bh[0] = sWh[nr * BQ_S + cb];
                bh[1] = sWh[nr * BQ_S + cb + 4];
                bl[0] = sWl[nr * BQ_S + cb];
                bl[1] = sWl[nr * BQ_S + cb + 4];
                #pragma unroll
                for (int mf = 0; mf < 4; mf++)
                    mma3_bf16(acc[mf][nf], ah[mf], al[mf], bh, bl);
            }
        }
    }

    #pragma unroll
    for (int nf = 0; nf < 4; nf++) {
        const int col = n0 + wn * 32 + nf * 8 + 2 * t4;
        const float b0 = bias[col], b1 = bias[col + 1];
        #pragma unroll
        for (int mf = 0; mf < 4; mf++) {
            const int r0 = m0 + wm * 64 + mf * 16 + g4;
            *(float2*)&C[(size_t)r0 * DM + col] =
                make_float2(acc[mf][nf][0] + b0, acc[mf][nf][1] + b1);
            *(float2*)&C[(size_t)(r0 + 8) * DM + col] =
                make_float2(acc[mf][nf][2] + b0, acc[mf][nf][3] + b1);
        }
    }
}

__global__ __launch_bounds__(256) void gemm_qkv(
    const float* __restrict__ x, const float* __restrict__ y,
    const float* __restrict__ q_w, const float* __restrict__ q_b,
    const float* __restrict__ k_w, const float* __restrict__ k_b,
    const float* __restrict__ v_w, const float* __restrict__ v_b,
    float* __restrict__ Qp, float* __restrict__ Kp, float* __restrict__ Vp)
{
    const float *A, *W, *bias;
    float* C;
    if (blockIdx.z == 0)      { A = x; W = q_w; bias = q_b; C = Qp; }
    else if (blockIdx.z == 1) { A = y; W = k_w; bias = k_b; C = Kp; }
    else                      { A = y; W = v_w; bias = v_b; C = Vp; }
    gemm_bf16_body(A, W, bias, C);
}

__global__ __launch_bounds__(256) void gemm_oproj(
    const float* __restrict__ A, const float* __restrict__ W,
    const float* __restrict__ bias, float* __restrict__ C)
{
    gemm_bf16_body(A, W, bias, C);
}

// ---------------------------------------------------------------------------
// K column-sum partials
// ---------------------------------------------------------------------------
__global__ __launch_bounds__(256) void ksum_kernel(const float* __restrict__ Kp,
                                                   float* __restrict__ out)
{
    const int g  = blockIdx.x;
    const int ch = blockIdx.y;
    const int d  = threadIdx.x & 63;
    const int rc = threadIdx.x >> 6;
    const float* Kg = Kp + ((size_t)g * SEQ + ch * 256) * HD;
    float s = 0.f;
    #pragma unroll 8
    for (int r = rc; r < 256; r += 4) s += Kg[r * HD + d];
    __shared__ float red[256];
    red[threadIdx.x] = s;
    __syncthreads();
    if (rc == 0)
        out[(g * 8 + ch) * HD + d] = red[d] + red[64 + d] + red[128 + d] + red[192 + d];
}

// ---------------------------------------------------------------------------
// Single-pass fused attention, double-buffered K/V SMEM:
//   scores: 3xBF16 (m16n8k16, hi/lo planes)  — 96 mma/tile-warp
//   P:      tf32-hi only, self-normalized
//   V:      tf32-hi only                      — 64 mma/tile-warp
// CTA = 128 query rows (256 threads, 8 warps x 16 rows).
// K planes: uint32 (bf16x2) stride 36/row -> B-frag banks (4*g4+t4) distinct.
// ---------------------------------------------------------------------------
#define AT_SK 36                                  // uint32 stride per K row
#define AT_SV 72
#define AT_S  68                                  // P float stride
#define KPLANE (64 * AT_SK)                       // uint32 per plane
#define KBUF_U32 (2 * KPLANE)                     // hi+lo per buffer
#define VBUF_F  (64 * AT_SV)
#define SM_BYTES (2 * KBUF_U32 * 4 + 2 * VBUF_F * 4 + 8 * 16 * AT_S * 4)

__global__ __launch_bounds__(256, 1) void attn_fused(
    const float* __restrict__ Qp, const float* __restrict__ Kp,
    const float* __restrict__ Vp, const float* __restrict__ KsP,
    float* __restrict__ AO)
{
    extern __shared__ uint32_t smu[];
    uint32_t* sKbuf = smu;                              // 2 x (hi,lo) planes
    float*  sVb = (float*)(smu + 2 * KBUF_U32);         // 2 x [64][AT_SV]
    float*  sP_all = sVb + 2 * VBUF_F;                  // 8 x [16][AT_S]

    const int tid  = threadIdx.x;
    const int warp = tid >> 5;
    const int lane = tid & 31;
    const int g4   = lane >> 2;
    const int t4   = lane & 3;

    const int mt  = blockIdx.x;
    const int grp = blockIdx.y;
    const float* Qg = Qp + (size_t)grp * SEQ * HD;
    const float* Kg = Kp + (size_t)grp * SEQ * HD;
    const float* Vg = Vp + (size_t)grp * SEQ * HD;
    float*       Og = AO + (size_t)grp * SEQ * HD;

    const int m0 = mt * 128;
    const int wrow = warp * 16;
    float* sPf = sP_all + warp * 16 * AT_S;

    // per-thread tile coords
    int trr[4], tcc[4];
    #pragma unroll
    for (int i = 0; i < 4; i++) {
        int j = tid + i * 256;
        trr[i] = j >> 4;
        tcc[i] = (j & 15) << 2;
    }

    // --- Q fragments (bf16 hi/lo, m16n8k16 A-layout) + row means ---
    const int row0 = m0 + wrow + g4;
    const int row1 = row0 + 8;
    uint32_t qah[4][4], qal[4][4];
    float mdot0 = 0.f, mdot1 = 0.f;

    #pragma unroll
    for (int ks = 0; ks < 4; ks++) {
        #pragma unroll
        for (int e = 0; e < 2; e++) {
            const int col = ks * 16 + e * 8 + 2 * t4;
            float ksum0 = 0.f, ksum1 = 0.f;
            #pragma unroll
            for (int c = 0; c < 8; c++) {
                ksum0 += KsP[(grp * 8 + c) * HD + col];
                ksum1 += KsP[(grp * 8 + c) * HD + col + 1];
            }
            float q0a = Qg[(size_t)row0 * HD + col];
            float q0b = Qg[(size_t)row0 * HD + col + 1];
            float q1a = Qg[(size_t)row1 * HD + col];
            float q1b = Qg[(size_t)row1 * HD + col + 1];
            mdot0 += q0a * ksum0 + q0b * ksum1;
            mdot1 += q1a * ksum0 + q1b * ksum1;
            split_bf16x2(q0a * NORMF, q0b * NORMF, qah[ks][e * 2], qal[ks][e * 2]);
            split_bf16x2(q1a * NORMF, q1b * NORMF, qah[ks][e * 2 + 1], qal[ks][e * 2 + 1]);
        }
    }
    #pragma unroll
    for (int o = 1; o <= 2; o <<= 1) {
        mdot0 += __shfl_xor_sync(0xffffffffu, mdot0, o);
        mdot1 += __shfl_xor_sync(0xffffffffu, mdot1, o);
    }
    const float mean0 = mdot0 * (NORMF / (float)SEQ);
    const float mean1 = mdot1 * (NORMF / (float)SEQ);

    float oacc[8][4];
    #pragma unroll
    for (int j = 0; j < 8; j++)
        #pragma unroll
        for (int c = 0; c < 4; c++) oacc[j][c] = 0.f;
    float den0 = 0.f, den1 = 0.f;

    // prologue: load tile 0, split/store into buffer 0
    float4 kbuf[4], vbuf[4];
    #pragma unroll
    for (int i = 0; i < 4; i++) {
        kbuf[i] = *(const float4*)&Kg[(size_t)trr[i] * HD + tcc[i]];
        vbuf[i] = *(const float4*)&Vg[(size_t)trr[i] * HD + tcc[i]];
    }
    {
        uint32_t* sKh = sKbuf;
        uint32_t* sKl = sKbuf + KPLANE;
        float*    sVf = sVb;
        #pragma unroll
        for (int i = 0; i < 4; i++) {
            uint32_t h0, l0, h1, l1;
            const int idx = trr[i] * AT_SK + (tcc[i] >> 1);
            split_bf16x2(kbuf[i].x, kbuf[i].y, h0, l0);
            split_bf16x2(kbuf[i].z, kbuf[i].w, h1, l1);
            sKh[idx] = h0; sKh[idx + 1] = h1;
            sKl[idx] = l0; sKl[idx + 1] = l1;
            float4 vh;
            vh.x = __uint_as_float(to_tf32(vbuf[i].x));
            vh.y = __uint_as_float(to_tf32(vbuf[i].y));
            vh.z = __uint_as_float(to_tf32(vbuf[i].z));
            vh.w = __uint_as_float(to_tf32(vbuf[i].w));
            *(float4*)&sVf[trr[i] * AT_SV + tcc[i]] = vh;
        }
    }
    __syncthreads();

    for (int kt = 0; kt < SEQ / 64; kt++) {
        const int cur = kt & 1;
        uint32_t* sKh = sKbuf + cur * KBUF_U32;
        uint32_t* sKl = sKh + KPLANE;
        float*    sVf = sVb + cur * VBUF_F;

        const bool more = (kt + 1 < SEQ / 64);
        if (more) {
            const size_t base = (size_t)(kt + 1) * 64;
            #pragma unroll
            for (int i = 0; i < 4; i++) {
                kbuf[i] = *(const float4*)&Kg[(base + trr[i]) * HD + tcc[i]];
                vbuf[i] = *(const float4*)&Vg[(base + trr[i]) * HD + tcc[i]];
            }
        }

        // S = Qs @ K^T (3xBF16, k16)
        float sacc[8][4];
        #pragma unroll
        for (int j = 0; j < 8; j++)
            #pragma unroll
            for (int c = 0; c < 4; c++) sacc[j][c] = 0.f;

        #pragma unroll
        for (int ks = 0; ks < 4; ks++) {
            const int kb = ks * 8;
            #pragma unroll
            for (int j = 0; j < 8; j++) {
                const int brow = j * 8 + g4;
                uint32_t bh[2], bl[2];
                bh[0] = sKh[brow * AT_SK + kb + t4];
                bh[1] = sKh[brow * AT_SK + kb + 4 + t4];
                bl[0] = sKl[brow * AT_SK + kb + t4];
                bl[1] = sKl[brow * AT_SK + kb + 4 + t4];
                mma3_bf16(sacc[j], qah[ks], qal[ks], bh, bl);
            }
        }

        // mask + exp -> quantize P to tf32-hi; denom from the SAME hi values
        #pragma unroll
        for (int j = 0; j < 8; j++) {
            float p0 = (sacc[j][0] > mean0) ? __expf(sacc[j][0]) : 0.f;
            float p1 = (sacc[j][1] > mean0) ? __expf(sacc[j][1]) : 0.f;
            float p2 = (sacc[j][2] > mean1) ? __expf(sacc[j][2]) : 0.f;
            float p3 = (sacc[j][3] > mean1) ? __expf(sacc[j][3]) : 0.f;
            float h0 = __uint_as_float(to_tf32(p0));
            float h1 = __uint_as_float(to_tf32(p1));
            float h2 = __uint_as_float(to_tf32(p2));
            float h3 = __uint_as_float(to_tf32(p3));
            den0 += h0 + h1;
            den1 += h2 + h3;
            *(float2*)&sPf[g4       * AT_S + j * 8 + 2 * t4] = make_float2(h0, h1);
            *(float2*)&sPf[(g4 + 8) * AT_S + j * 8 + 2 * t4] = make_float2(h2, h3);
        }
        __syncwarp();

        // O += P_hi @ V_hi  (tf32 k8)
        #pragma unroll
        for (int kk = 0; kk < 8; kk++) {
            const int k0 = kk * 8;
            uint32_t ah[4];
            ah[0] = __float_as_uint(sPf[g4       * AT_S + k0 + t4]);
            ah[1] = __float_as_uint(sPf[(g4 + 8) * AT_S + k0 + t4]);
            ah[2] = __float_as_uint(sPf[g4       * AT_S + k0 + t4 + 4]);
            ah[3] = __float_as_uint(sPf[(g4 + 8) * AT_S + k0 + t4 + 4]);
            #pragma unroll
            for (int j = 0; j < 8; j++) {
                const int bcol = j * 8 + g4;
                uint32_t bh[2];
                bh[0] = __float_as_uint(sVf[(k0 + t4)     * AT_SV + bcol]);
                bh[1] = __float_as_uint(sVf[(k0 + t4 + 4) * AT_SV + bcol]);
                mma_tf32(oacc[j], ah, bh);
            }
        }

        // store prefetched tile into the OTHER buffer; single sync per tile
        if (more) {
            uint32_t* nKh = sKbuf + (1 - cur) * KBUF_U32;
            uint32_t* nKl = nKh + KPLANE;
            float*    nVf = sVb + (1 - cur) * VBUF_F;
            #pragma unroll
            for (int i = 0; i < 4; i++) {
                uint32_t h0, l0, h1, l1;
                const int idx = trr[i] * AT_SK + (tcc[i] >> 1);
                split_bf16x2(kbuf[i].x, kbuf[i].y, h0, l0);
                split_bf16x2(kbuf[i].z, kbuf[i].w, h1, l1);
                nKh[idx] = h0; nKh[idx + 1] = h1;
                nKl[idx] = l0; nKl[idx + 1] = l1;
                float4 vh;
                vh.x = __uint_as_float(to_tf32(vbuf[i].x));
                vh.y = __uint_as_float(to_tf32(vbuf[i].y));
                vh.z = __uint_as_float(to_tf32(vbuf[i].z));
                vh.w = __uint_as_float(to_tf32(vbuf[i].w));
                *(float4*)&nVf[trr[i] * AT_SV + tcc[i]] = vh;
            }
            __syncthreads();
        }
    }

    // reduce denominators, normalize, write out
    #pragma unroll
    for (int o = 1; o <= 2; o <<= 1) {
        den0 += __shfl_xor_sync(0xffffffffu, den0, o);
        den1 += __shfl_xor_sync(0xffffffffu, den1, o);
    }
    const float inv0 = 1.f / den0;
    const float inv1 = 1.f / den1;

    #pragma unroll
    for (int j = 0; j < 8; j++) {
        const int col = j * 8 + 2 * t4;
        *(float2*)&Og[(size_t)row0 * HD + col] =
            make_float2(oacc[j][0] * inv0, oacc[j][1] * inv0);
        *(float2*)&Og[(size_t)row1 * HD + col] =
            make_float2(oacc[j][2] * inv1, oacc[j][3] * inv1);
    }
}

// ---------------------------------------------------------------------------
// Launch
// ---------------------------------------------------------------------------
extern "C" void kernel_launch(void* const* d_in, const int* in_sizes, int n_in,
                              void* d_out, int out_size)
{
    const float* x   = (const float*)d_in[0];
    const float* y   = (const float*)d_in[1];
    const float* q_w = (const float*)d_in[2];
    const float* q_b = (const float*)d_in[3];
    const float* k_w = (const float*)d_in[4];
    const float* k_b = (const float*)d_in[5];
    const float* v_w = (const float*)d_in[6];
    const float* v_b = (const float*)d_in[7];
    const float* o_w = (const float*)d_in[8];
    const float* o_b = (const float*)d_in[9];
    float* out = (float*)d_out;

    float *Qp, *Kp, *Vp, *AO, *KsP;
    cudaGetSymbolAddress((void**)&Qp, g_Qp);
    cudaGetSymbolAddress((void**)&Kp, g_Kp);
    cudaGetSymbolAddress((void**)&Vp, g_Vp);
    cudaGetSymbolAddress((void**)&AO, g_AO);
    cudaGetSymbolAddress((void**)&KsP, g_KsumP);

    static int smem_set = 0;
    if (!smem_set) {
        cudaFuncSetAttribute(attn_fused,
                             cudaFuncAttributeMaxDynamicSharedMemorySize, SM_BYTES);
        smem_set = 1;
    }

    // Fused Q/K/V projections (3xBF16 tensor core) — one launch, 384 CTAs
    gemm_qkv<<<dim3(4, 32, 3), 256>>>(
        x, y, q_w, q_b, k_w, k_b, v_w, v_b, Qp, Kp, Vp);

    // K column-sum partials (for mean thresholds)
    ksum_kernel<<<dim3(NG, 8), 256>>>(Kp, KsP);

    // Fused single-pass attention (128 Q rows per CTA, double-buffered,
    // 3xBF16 scores + tf32-hi PV)
    attn_fused<<<dim3(SEQ / 128, NG), 256, SM_BYTES>>>(Qp, Kp, Vp, KsP, AO);

    // Output projection (3xBF16 tensor core)
    gemm_oproj<<<dim3(4, 32), 256>>>(AO, o_w, o_b, out);
}